// round 4
// baseline (speedup 1.0000x reference)
#include <cuda_runtime.h>
#include <mma.h>
#include <math.h>

using namespace nvcuda;

// Problem constants
#define BB    4
#define NN    2048
#define DD    256
#define HH    4
#define DHH   64
#define BH    16
#define MTOT  8192
#define QKSCALE 0.35355339059327379f  // 64^{-0.25}

// -------- scratch ----------
__device__ float g_qk[2][BH * NN * DHH];
__device__ float g_v [2][BH * NN * DHH];
__device__ float g_att[2][MTOT * DD];
__device__ float g_m [2][MTOT * DD];
__device__ float g_h [2][MTOT * 2 * DD];

using FragA  = wmma::fragment<wmma::matrix_a, 16, 16, 8, wmma::precision::tf32, wmma::row_major>;
using FragB  = wmma::fragment<wmma::matrix_b, 16, 16, 8, wmma::precision::tf32, wmma::row_major>;
using FragBc = wmma::fragment<wmma::matrix_b, 16, 16, 8, wmma::precision::tf32, wmma::col_major>;
using FragC  = wmma::fragment<wmma::accumulator, 16, 16, 8, float>;

__device__ __forceinline__ float4 tf32x4(float4 v) {
    v.x = wmma::__float_to_tf32(v.x);
    v.y = wmma::__float_to_tf32(v.y);
    v.z = wmma::__float_to_tf32(v.z);
    v.w = wmma::__float_to_tf32(v.w);
    return v;
}

// ==========================================================================
// Generic TF32 GEMM block: BM=128, BN=128, BK=16, 256 thr = 8 warps (2x4),
// warp tile 64x32.  Elements are pre-rounded to TF32 at staging time, so
// no per-fragment conversion in the mainloop.
// ==========================================================================
#define AS_LD 24
#define BS_LD 136
#define ST_LD 20

__device__ __forceinline__ void gemm_core(const float* As, const float* Bs,
                                          FragC acc[4][2], int wr, int wc)
{
#pragma unroll
    for (int kk = 0; kk < 2; kk++) {
        FragA af[4];
        FragB bf[2];
#pragma unroll
        for (int i = 0; i < 4; i++)
            wmma::load_matrix_sync(af[i], As + (wr * 64 + i * 16) * AS_LD + kk * 8, AS_LD);
#pragma unroll
        for (int j = 0; j < 2; j++)
            wmma::load_matrix_sync(bf[j], Bs + (kk * 8) * BS_LD + wc * 32 + j * 16, BS_LD);
#pragma unroll
        for (int i = 0; i < 4; i++)
#pragma unroll
            for (int j = 0; j < 2; j++)
                wmma::mma_sync(acc[i][j], af[i], bf[j], acc[i][j]);
    }
}

// register prefetch: A tile (128x16), B tile (16x128), 2 float4 each / thread
__device__ __forceinline__ void ldg_A(float4 r[2], const float* A, int mBase,
                                      int kt, int lda, int tid)
{
#pragma unroll
    for (int it = 0; it < 2; it++) {
        int i = tid + it * 256;
        int row = i >> 2, c4 = i & 3;
        r[it] = *(const float4*)(A + (size_t)(mBase + row) * lda + kt + c4 * 4);
    }
}
__device__ __forceinline__ void sts_A(float* As, const float4 r[2], int tid)
{
#pragma unroll
    for (int it = 0; it < 2; it++) {
        int i = tid + it * 256;
        int row = i >> 2, c4 = i & 3;
        *(float4*)(As + row * AS_LD + c4 * 4) = tf32x4(r[it]);
    }
}
__device__ __forceinline__ void ldg_B(float4 r[2], const float* B, int kt,
                                      int cOff, int ldb, int tid)
{
#pragma unroll
    for (int it = 0; it < 2; it++) {
        int i = tid + it * 256;
        int k = i >> 5, c4 = i & 31;
        r[it] = *(const float4*)(B + (size_t)(kt + k) * ldb + cOff + c4 * 4);
    }
}
__device__ __forceinline__ void sts_B(float* Bs, const float4 r[2], int tid)
{
#pragma unroll
    for (int it = 0; it < 2; it++) {
        int i = tid + it * 256;
        int k = i >> 5, c4 = i & 31;
        *(float4*)(Bs + k * BS_LD + c4 * 4) = tf32x4(r[it]);
    }
}

// ==========================================================================
// Kernel 1: fused QK/V projection. grid (4, 64, 2) block 256
// ==========================================================================
__global__ __launch_bounds__(256) void qkv_kernel(
    const float* __restrict__ x0, const float* __restrict__ x1,
    const float* __restrict__ w_qk, const float* __restrict__ b_qk,
    const float* __restrict__ w_v,  const float* __restrict__ b_v)
{
    __shared__ float As[128 * AS_LD];
    __shared__ float Bs[16 * BS_LD];
    __shared__ float stage[8][16 * ST_LD];

    const int s = blockIdx.z;
    const float* A = s ? x1 : x0;
    const int mBase = blockIdx.y * 128;
    const int cBase = blockIdx.x * 128;
    const int tid = threadIdx.x;
    const int warp = tid >> 5, lane = tid & 31;
    const int wr = warp >> 2, wc = warp & 3;

    const float* W; int cOff;
    if (cBase < 256) { W = w_qk; cOff = cBase; }
    else             { W = w_v;  cOff = cBase - 256; }

    FragC acc[4][2];
#pragma unroll
    for (int i = 0; i < 4; i++)
#pragma unroll
        for (int j = 0; j < 2; j++) wmma::fill_fragment(acc[i][j], 0.f);

    float4 aR[2], bR[2];
    ldg_A(aR, A, mBase, 0, DD, tid);
    ldg_B(bR, W, 0, cOff, DD, tid);
    sts_A(As, aR, tid);
    sts_B(Bs, bR, tid);
    __syncthreads();

    for (int kt = 0; kt < 256; kt += 16) {
        bool nxt = (kt + 16) < 256;
        if (nxt) {
            ldg_A(aR, A, mBase, kt + 16, DD, tid);
            ldg_B(bR, W, kt + 16, cOff, DD, tid);
        }
        gemm_core(As, Bs, acc, wr, wc);
        __syncthreads();
        if (nxt) {
            sts_A(As, aR, tid);
            sts_B(Bs, bR, tid);
            __syncthreads();
        }
    }

    float* stg = stage[warp];
    const int r = lane >> 1, c0 = (lane & 1) * 8;
#pragma unroll
    for (int i = 0; i < 4; i++)
#pragma unroll
        for (int j = 0; j < 2; j++) {
            wmma::store_matrix_sync(stg, acc[i][j], ST_LD, wmma::mem_row_major);
            __syncwarp();
            int gm = mBase + wr * 64 + i * 16 + r;
            int gc = cBase + wc * 32 + j * 16 + c0;
            int b = gm >> 11, n = gm & 2047;
#pragma unroll
            for (int u = 0; u < 8; u++) {
                float v = stg[r * ST_LD + c0 + u];
                int c = gc + u;
                if (c < 256) {
                    int h = c >> 6, d = c & 63;
                    g_qk[s][(((size_t)(b * HH + h) * NN + n) * DHH) + d] =
                        (v + b_qk[c]) * QKSCALE;
                } else {
                    int c2 = c - 256;
                    int h = c2 >> 6, d = c2 & 63;
                    g_v[s][(((size_t)(b * HH + h) * NN + n) * DHH) + d] = v + b_v[c2];
                }
            }
            __syncwarp();
        }
}

// ==========================================================================
// Kernel 2: attention (TF32, no-max softmax — sim entries are O(0.1)).
// grid (16, 16, 2) block 256.  Register-prefetched K/V tiles.
// ==========================================================================
#define AT_LD 72
#define ATTN_SMEM ((64 * AT_LD * 2 + 128 * AT_LD) * 4)

__global__ __launch_bounds__(256) void attn_kernel()
{
    extern __shared__ float sm[];
    float* Ks = sm;
    float* Vs = sm + 64 * AT_LD;
    float* Ps = sm + 2 * 64 * AT_LD;

    const int s  = blockIdx.z;
    const int bh = blockIdx.y;
    const int qb = blockIdx.x;
    const float* Q = g_qk[s]     + (size_t)bh * NN * DHH + (size_t)qb * 128 * DHH;
    const float* K = g_qk[s ^ 1] + (size_t)bh * NN * DHH;
    const float* V = g_v [s ^ 1] + (size_t)bh * NN * DHH;

    const int tid = threadIdx.x;
    const int w = tid >> 5;

    // stage Q (pre-rounded) into Ps
#pragma unroll
    for (int it = 0; it < 8; it++) {
        int i = tid + it * 256;
        int r = i >> 4, c4 = i & 15;
        *(float4*)(Ps + r * AT_LD + c4 * 4) =
            tf32x4(*(const float4*)(Q + r * 64 + c4 * 4));
    }
    __syncthreads();

    FragA qf[8];
#pragma unroll
    for (int kk = 0; kk < 8; kk++)
        wmma::load_matrix_sync(qf[kk], Ps + (w * 16) * AT_LD + kk * 8, AT_LD);

    // prefetch + stage KV block 0
    float4 kR[4], vR[4];
#pragma unroll
    for (int it = 0; it < 4; it++) {
        int i = tid + it * 256;
        int r = i >> 4, c4 = i & 15;
        kR[it] = *(const float4*)(K + r * 64 + c4 * 4);
        vR[it] = *(const float4*)(V + r * 64 + c4 * 4);
    }
#pragma unroll
    for (int it = 0; it < 4; it++) {
        int i = tid + it * 256;
        int r = i >> 4, c4 = i & 15;
        *(float4*)(Ks + r * AT_LD + c4 * 4) = tf32x4(kR[it]);
        *(float4*)(Vs + r * AT_LD + c4 * 4) = tf32x4(vR[it]);
    }
    __syncthreads();   // covers qf reads of Ps and KV staging

    FragC o[4];
#pragma unroll
    for (int c = 0; c < 4; c++) wmma::fill_fragment(o[c], 0.f);
    float lsum = 0.f;

    const int erow = tid >> 1;
    const int ecb  = (tid & 1) * 32;

    for (int kb = 0; kb < NN / 64; kb++) {
        bool nxt = (kb + 1) < NN / 64;
        if (nxt) {
            const float* Kb = K + (size_t)(kb + 1) * 64 * 64;
            const float* Vb = V + (size_t)(kb + 1) * 64 * 64;
#pragma unroll
            for (int it = 0; it < 4; it++) {
                int i = tid + it * 256;
                int r = i >> 4, c4 = i & 15;
                kR[it] = *(const float4*)(Kb + r * 64 + c4 * 4);
                vR[it] = *(const float4*)(Vb + r * 64 + c4 * 4);
            }
        }

        // S = Q @ K^T (per warp 16x64)
        FragC sa[4];
#pragma unroll
        for (int c = 0; c < 4; c++) wmma::fill_fragment(sa[c], 0.f);
#pragma unroll
        for (int kk = 0; kk < 8; kk++) {
#pragma unroll
            for (int c = 0; c < 4; c++) {
                FragBc bf;
                wmma::load_matrix_sync(bf, Ks + (c * 16) * AT_LD + kk * 8, AT_LD);
                wmma::mma_sync(sa[c], qf[kk], bf, sa[c]);
            }
        }
#pragma unroll
        for (int c = 0; c < 4; c++)
            wmma::store_matrix_sync(Ps + (w * 16) * AT_LD + c * 16, sa[c], AT_LD,
                                    wmma::mem_row_major);
        __syncthreads();

        // P = exp(S) (rounded to tf32), partial sums
        {
            float rs = 0.f;
#pragma unroll
            for (int c = 0; c < 32; c++) {
                float p = wmma::__float_to_tf32(__expf(Ps[erow * AT_LD + ecb + c]));
                Ps[erow * AT_LD + ecb + c] = p;
                rs += p;
            }
            rs += __shfl_xor_sync(0xffffffffu, rs, 1);
            lsum += rs;
        }
        __syncthreads();

        // O += P @ V
#pragma unroll
        for (int kk = 0; kk < 8; kk++) {
            FragA af;
            wmma::load_matrix_sync(af, Ps + (w * 16) * AT_LD + kk * 8, AT_LD);
#pragma unroll
            for (int c = 0; c < 4; c++) {
                FragB bf;
                wmma::load_matrix_sync(bf, Vs + (kk * 8) * AT_LD + c * 16, AT_LD);
                wmma::mma_sync(o[c], af, bf, o[c]);
            }
        }
        __syncthreads();   // all reads of Ks/Vs/Ps done

        if (nxt) {
#pragma unroll
            for (int it = 0; it < 4; it++) {
                int i = tid + it * 256;
                int r = i >> 4, c4 = i & 15;
                *(float4*)(Ks + r * AT_LD + c4 * 4) = tf32x4(kR[it]);
                *(float4*)(Vs + r * AT_LD + c4 * 4) = tf32x4(vR[it]);
            }
            __syncthreads();
        }
    }

    // finalize
#pragma unroll
    for (int c = 0; c < 4; c++)
        wmma::store_matrix_sync(Ps + (w * 16) * AT_LD + c * 16, o[c], AT_LD,
                                wmma::mem_row_major);
    __syncthreads();

    const int b = bh >> 2, h = bh & 3;
    {
        float inv = 1.f / lsum;
        int n = qb * 128 + erow;
        float* dst = g_att[s] + ((size_t)(b * NN + n)) * DD + h * 64 + ecb;
        const float* src = Ps + erow * AT_LD + ecb;
#pragma unroll
        for (int c4 = 0; c4 < 8; c4++) {
            float4 v = *(const float4*)(src + c4 * 4);
            v.x *= inv; v.y *= inv; v.z *= inv; v.w *= inv;
            *(float4*)(dst + c4 * 4) = v;
        }
    }
}

// ==========================================================================
// Kernel 3: out projection. grid (2, 64, 2) block 256
// ==========================================================================
__global__ __launch_bounds__(256) void outproj_kernel(
    const float* __restrict__ w, const float* __restrict__ bias)
{
    __shared__ float As[128 * AS_LD];
    __shared__ float Bs[16 * BS_LD];
    __shared__ float stage[8][16 * ST_LD];

    const int s = blockIdx.z;
    const float* A = g_att[s];
    const int mBase = blockIdx.y * 128;
    const int cBase = blockIdx.x * 128;
    const int tid = threadIdx.x;
    const int warp = tid >> 5, lane = tid & 31;
    const int wr = warp >> 2, wc = warp & 3;

    FragC acc[4][2];
#pragma unroll
    for (int i = 0; i < 4; i++)
#pragma unroll
        for (int j = 0; j < 2; j++) wmma::fill_fragment(acc[i][j], 0.f);

    float4 aR[2], bR[2];
    ldg_A(aR, A, mBase, 0, DD, tid);
    ldg_B(bR, w, 0, cBase, DD, tid);
    sts_A(As, aR, tid);
    sts_B(Bs, bR, tid);
    __syncthreads();

    for (int kt = 0; kt < 256; kt += 16) {
        bool nxt = (kt + 16) < 256;
        if (nxt) {
            ldg_A(aR, A, mBase, kt + 16, DD, tid);
            ldg_B(bR, w, kt + 16, cBase, DD, tid);
        }
        gemm_core(As, Bs, acc, wr, wc);
        __syncthreads();
        if (nxt) {
            sts_A(As, aR, tid);
            sts_B(Bs, bR, tid);
            __syncthreads();
        }
    }

    float* stg = stage[warp];
    const int r = lane >> 1, c0 = (lane & 1) * 8;
#pragma unroll
    for (int i = 0; i < 4; i++)
#pragma unroll
        for (int j = 0; j < 2; j++) {
            wmma::store_matrix_sync(stg, acc[i][j], ST_LD, wmma::mem_row_major);
            __syncwarp();
            int gm = mBase + wr * 64 + i * 16 + r;
            int gc = cBase + wc * 32 + j * 16 + c0;
            float4 b0 = *(const float4*)(bias + gc);
            float4 b1 = *(const float4*)(bias + gc + 4);
            const float* sp = stg + r * ST_LD + c0;
            float4 v0 = make_float4(sp[0] + b0.x, sp[1] + b0.y, sp[2] + b0.z, sp[3] + b0.w);
            float4 v1 = make_float4(sp[4] + b1.x, sp[5] + b1.y, sp[6] + b1.z, sp[7] + b1.w);
            *(float4*)(&g_m[s][(size_t)gm * DD + gc])     = v0;
            *(float4*)(&g_m[s][(size_t)gm * DD + gc + 4]) = v1;
            __syncwarp();
        }
}

// ==========================================================================
// Kernel 4: FFN1.  h = [x | m] @ w_f1 + b_f1  (K=512). grid (4, 64, 2)
// ==========================================================================
__global__ __launch_bounds__(256) void ffn1_kernel(
    const float* __restrict__ x0, const float* __restrict__ x1,
    const float* __restrict__ w, const float* __restrict__ bias)
{
    __shared__ float As[128 * AS_LD];
    __shared__ float Bs[16 * BS_LD];
    __shared__ float stage[8][16 * ST_LD];

    const int s = blockIdx.z;
    const float* X  = s ? x1 : x0;
    const float* Mm = g_m[s];
    const int mBase = blockIdx.y * 128;
    const int cBase = blockIdx.x * 128;
    const int tid = threadIdx.x;
    const int warp = tid >> 5, lane = tid & 31;
    const int wr = warp >> 2, wc = warp & 3;

    FragC acc[4][2];
#pragma unroll
    for (int i = 0; i < 4; i++)
#pragma unroll
        for (int j = 0; j < 2; j++) wmma::fill_fragment(acc[i][j], 0.f);

    float4 aR[2], bR[2];
    ldg_A(aR, X, mBase, 0, DD, tid);
    ldg_B(bR, w, 0, cBase, 2 * DD, tid);
    sts_A(As, aR, tid);
    sts_B(Bs, bR, tid);
    __syncthreads();

    for (int kt = 0; kt < 512; kt += 16) {
        bool nxt = (kt + 16) < 512;
        if (nxt) {
            int kn = kt + 16;
            const float* Asrc = (kn < 256) ? X : Mm;
            int kOff = (kn < 256) ? kn : kn - 256;
            ldg_A(aR, Asrc, mBase, kOff, DD, tid);
            ldg_B(bR, w, kn, cBase, 2 * DD, tid);
        }
        gemm_core(As, Bs, acc, wr, wc);
        __syncthreads();
        if (nxt) {
            sts_A(As, aR, tid);
            sts_B(Bs, bR, tid);
            __syncthreads();
        }
    }

    float* stg = stage[warp];
    const int r = lane >> 1, c0 = (lane & 1) * 8;
#pragma unroll
    for (int i = 0; i < 4; i++)
#pragma unroll
        for (int j = 0; j < 2; j++) {
            wmma::store_matrix_sync(stg, acc[i][j], ST_LD, wmma::mem_row_major);
            __syncwarp();
            int gm = mBase + wr * 64 + i * 16 + r;
            int gc = cBase + wc * 32 + j * 16 + c0;
            float4 b0 = *(const float4*)(bias + gc);
            float4 b1 = *(const float4*)(bias + gc + 4);
            const float* sp = stg + r * ST_LD + c0;
            float4 v0 = make_float4(sp[0] + b0.x, sp[1] + b0.y, sp[2] + b0.z, sp[3] + b0.w);
            float4 v1 = make_float4(sp[4] + b1.x, sp[5] + b1.y, sp[6] + b1.z, sp[7] + b1.w);
            *(float4*)(&g_h[s][(size_t)gm * (2 * DD) + gc])     = v0;
            *(float4*)(&g_h[s][(size_t)gm * (2 * DD) + gc + 4]) = v1;
            __syncwarp();
        }
}

// ==========================================================================
// Kernel 5: LayerNorm(512) + exact GELU, in place. grid 16384 block 128
// ==========================================================================
__global__ __launch_bounds__(128) void ln_gelu_kernel(
    const float* __restrict__ g, const float* __restrict__ bta)
{
    const int row = blockIdx.x;
    const int s = row >> 13;
    float* h = g_h[s] + (size_t)(row & 8191) * 512;
    const int tid = threadIdx.x;

    float4 t = reinterpret_cast<float4*>(h)[tid];
    float sum = t.x + t.y + t.z + t.w;
    float sq  = t.x * t.x + t.y * t.y + t.z * t.z + t.w * t.w;
#pragma unroll
    for (int off = 16; off > 0; off >>= 1) {
        sum += __shfl_xor_sync(0xffffffffu, sum, off);
        sq  += __shfl_xor_sync(0xffffffffu, sq,  off);
    }
    __shared__ float ssum[4], ssq[4];
    const int w = tid >> 5;
    if ((tid & 31) == 0) { ssum[w] = sum; ssq[w] = sq; }
    __syncthreads();
    sum = ssum[0] + ssum[1] + ssum[2] + ssum[3];
    sq  = ssq[0]  + ssq[1]  + ssq[2]  + ssq[3];

    const float mu   = sum * (1.f / 512.f);
    const float var  = sq * (1.f / 512.f) - mu * mu;
    const float rstd = rsqrtf(var + 1e-5f);

    float4 gg = reinterpret_cast<const float4*>(g)[tid];
    float4 bb = reinterpret_cast<const float4*>(bta)[tid];
    auto act = [&](float v, float gv, float bv) {
        float y = (v - mu) * rstd * gv + bv;
        return 0.5f * y * (1.f + erff(y * 0.70710678118654752f));
    };
    t.x = act(t.x, gg.x, bb.x);
    t.y = act(t.y, gg.y, bb.y);
    t.z = act(t.z, gg.z, bb.z);
    t.w = act(t.w, gg.w, bb.w);
    reinterpret_cast<float4*>(h)[tid] = t;
}

// ==========================================================================
// Kernel 6: FFN2 + residual.  out = x + h @ w_f2 + b_f2 (K=512). grid (2,64,2)
// ==========================================================================
__global__ __launch_bounds__(256) void ffn2_kernel(
    const float* __restrict__ x0, const float* __restrict__ x1,
    const float* __restrict__ w, const float* __restrict__ bias,
    float* __restrict__ out)
{
    __shared__ float As[128 * AS_LD];
    __shared__ float Bs[16 * BS_LD];
    __shared__ float stage[8][16 * ST_LD];

    const int s = blockIdx.z;
    const float* X = s ? x1 : x0;
    const float* A = g_h[s];
    const int mBase = blockIdx.y * 128;
    const int cBase = blockIdx.x * 128;
    const int tid = threadIdx.x;
    const int warp = tid >> 5, lane = tid & 31;
    const int wr = warp >> 2, wc = warp & 3;

    FragC acc[4][2];
#pragma unroll
    for (int i = 0; i < 4; i++)
#pragma unroll
        for (int j = 0; j < 2; j++) wmma::fill_fragment(acc[i][j], 0.f);

    float4 aR[2], bR[2];
    ldg_A(aR, A, mBase, 0, 2 * DD, tid);
    ldg_B(bR, w, 0, cBase, DD, tid);
    sts_A(As, aR, tid);
    sts_B(Bs, bR, tid);
    __syncthreads();

    for (int kt = 0; kt < 512; kt += 16) {
        bool nxt = (kt + 16) < 512;
        if (nxt) {
            ldg_A(aR, A, mBase, kt + 16, 2 * DD, tid);
            ldg_B(bR, w, kt + 16, cBase, DD, tid);
        }
        gemm_core(As, Bs, acc, wr, wc);
        __syncthreads();
        if (nxt) {
            sts_A(As, aR, tid);
            sts_B(Bs, bR, tid);
            __syncthreads();
        }
    }

    float* stg = stage[warp];
    const int r = lane >> 1, c0 = (lane & 1) * 8;
#pragma unroll
    for (int i = 0; i < 4; i++)
#pragma unroll
        for (int j = 0; j < 2; j++) {
            wmma::store_matrix_sync(stg, acc[i][j], ST_LD, wmma::mem_row_major);
            __syncwarp();
            int gm = mBase + wr * 64 + i * 16 + r;
            int gc = cBase + wc * 32 + j * 16 + c0;
            float4 b0 = *(const float4*)(bias + gc);
            float4 b1 = *(const float4*)(bias + gc + 4);
            float4 x0v = *(const float4*)(X + (size_t)gm * DD + gc);
            float4 x1v = *(const float4*)(X + (size_t)gm * DD + gc + 4);
            const float* sp = stg + r * ST_LD + c0;
            float4 v0 = make_float4(sp[0] + b0.x + x0v.x, sp[1] + b0.y + x0v.y,
                                    sp[2] + b0.z + x0v.z, sp[3] + b0.w + x0v.w);
            float4 v1 = make_float4(sp[4] + b1.x + x1v.x, sp[5] + b1.y + x1v.y,
                                    sp[6] + b1.z + x1v.z, sp[7] + b1.w + x1v.w);
            *(float4*)(out + (size_t)s * MTOT * DD + (size_t)gm * DD + gc)     = v0;
            *(float4*)(out + (size_t)s * MTOT * DD + (size_t)gm * DD + gc + 4) = v1;
            __syncwarp();
        }
}

// ==========================================================================
extern "C" void kernel_launch(void* const* d_in, const int* in_sizes, int n_in,
                              void* d_out, int out_size)
{
    const float* x0    = (const float*)d_in[0];
    const float* x1    = (const float*)d_in[1];
    const float* w_qk  = (const float*)d_in[2];
    const float* b_qk  = (const float*)d_in[3];
    const float* w_v   = (const float*)d_in[4];
    const float* b_v   = (const float*)d_in[5];
    const float* w_out = (const float*)d_in[6];
    const float* b_out = (const float*)d_in[7];
    const float* w_f1  = (const float*)d_in[8];
    const float* b_f1  = (const float*)d_in[9];
    const float* ln_g  = (const float*)d_in[10];
    const float* ln_b  = (const float*)d_in[11];
    const float* w_f2  = (const float*)d_in[12];
    const float* b_f2  = (const float*)d_in[13];
    float* out = (float*)d_out;

    cudaFuncSetAttribute(attn_kernel,
                         cudaFuncAttributeMaxDynamicSharedMemorySize, ATTN_SMEM);

    qkv_kernel    <<<dim3(4, 64, 2), 256>>>(x0, x1, w_qk, b_qk, w_v, b_v);
    attn_kernel   <<<dim3(16, 16, 2), 256, ATTN_SMEM>>>();
    outproj_kernel<<<dim3(2, 64, 2), 256>>>(w_out, b_out);
    ffn1_kernel   <<<dim3(4, 64, 2), 256>>>(x0, x1, w_f1, b_f1);
    ln_gelu_kernel<<<16384, 128>>>(ln_g, ln_b);
    ffn2_kernel   <<<dim3(2, 64, 2), 256>>>(x0, x1, w_f2, b_f2, out);
}

// round 6
// speedup vs baseline: 1.2395x; 1.2395x over previous
#include <cuda_runtime.h>
#include <mma.h>
#include <math.h>

using namespace nvcuda;

// Problem constants
#define BB    4
#define NN    2048
#define DD    256
#define HH    4
#define DHH   64
#define BH    16
#define MTOT  8192
#define QKSCALE 0.35355339059327379f  // 64^{-0.25}

// -------- scratch ----------
__device__ float g_qk[2][BH * NN * DHH];
__device__ float g_v [2][BH * NN * DHH];
__device__ float g_att[2][MTOT * DD];
__device__ float g_m [2][MTOT * DD];
__device__ float g_h [2][MTOT * 2 * DD];

using FragA  = wmma::fragment<wmma::matrix_a, 16, 16, 8, wmma::precision::tf32, wmma::row_major>;
using FragB  = wmma::fragment<wmma::matrix_b, 16, 16, 8, wmma::precision::tf32, wmma::row_major>;
using FragBc = wmma::fragment<wmma::matrix_b, 16, 16, 8, wmma::precision::tf32, wmma::col_major>;
using FragC  = wmma::fragment<wmma::accumulator, 16, 16, 8, float>;

// ---- cp.async helpers ----
__device__ __forceinline__ void cp16(float* smem_dst, const float* gsrc) {
    unsigned int s = (unsigned int)__cvta_generic_to_shared(smem_dst);
    asm volatile("cp.async.cg.shared.global [%0], [%1], 16;" :: "r"(s), "l"(gsrc));
}
#define CP_COMMIT() asm volatile("cp.async.commit_group;")
#define CP_WAIT0()  asm volatile("cp.async.wait_group 0;")

// ==========================================================================
// TF32 GEMM block: BM=128, BN=128, BK=16, 256 thr = 8 warps (2x4),
// warp tile 64x32.  2-stage cp.async pipeline, ONE __syncthreads per K-step.
// Raw f32 in smem; HMMA.TF32 truncates mantissa in hardware (no cvt).
// ==========================================================================
#define AS_LD 24
#define BS_LD 136
#define ST_LD 20

__device__ __forceinline__ void gemm_core(const float* As, const float* Bs,
                                          FragC acc[4][2], int wr, int wc)
{
#pragma unroll
    for (int kk = 0; kk < 2; kk++) {
        FragA af[4];
        FragB bf[2];
#pragma unroll
        for (int i = 0; i < 4; i++)
            wmma::load_matrix_sync(af[i], As + (wr * 64 + i * 16) * AS_LD + kk * 8, AS_LD);
#pragma unroll
        for (int j = 0; j < 2; j++)
            wmma::load_matrix_sync(bf[j], Bs + (kk * 8) * BS_LD + wc * 32 + j * 16, BS_LD);
#pragma unroll
        for (int i = 0; i < 4; i++)
#pragma unroll
            for (int j = 0; j < 2; j++)
                wmma::mma_sync(acc[i][j], af[i], bf[j], acc[i][j]);
    }
}

__device__ __forceinline__ void issue_A(float* As, const float* A, int mBase,
                                        int kt, int lda, int tid)
{
#pragma unroll
    for (int it = 0; it < 2; it++) {
        int i = tid + it * 256;
        int row = i >> 2, c4 = i & 3;
        cp16(As + row * AS_LD + c4 * 4, A + (size_t)(mBase + row) * lda + kt + c4 * 4);
    }
}
__device__ __forceinline__ void issue_B(float* Bs, const float* B, int kt,
                                        int cOff, int ldb, int tid)
{
#pragma unroll
    for (int it = 0; it < 2; it++) {
        int i = tid + it * 256;
        int k = i >> 5, c4 = i & 31;
        cp16(Bs + k * BS_LD + c4 * 4, B + (size_t)(kt + k) * ldb + cOff + c4 * 4);
    }
}

// ==========================================================================
// Kernel 1: fused QK/V projection. grid (4, 64, 2) block 256
// ==========================================================================
__global__ __launch_bounds__(256) void qkv_kernel(
    const float* __restrict__ x0, const float* __restrict__ x1,
    const float* __restrict__ w_qk, const float* __restrict__ b_qk,
    const float* __restrict__ w_v,  const float* __restrict__ b_v)
{
    __shared__ float As[2][128 * AS_LD];
    __shared__ float Bs[2][16 * BS_LD];

    const int s = blockIdx.z;
    const float* A = s ? x1 : x0;
    const int mBase = blockIdx.y * 128;
    const int cBase = blockIdx.x * 128;
    const int tid = threadIdx.x;
    const int warp = tid >> 5, lane = tid & 31;
    const int wr = warp >> 2, wc = warp & 3;

    const float* W; int cOff;
    if (cBase < 256) { W = w_qk; cOff = cBase; }
    else             { W = w_v;  cOff = cBase - 256; }

    FragC acc[4][2];
#pragma unroll
    for (int i = 0; i < 4; i++)
#pragma unroll
        for (int j = 0; j < 2; j++) wmma::fill_fragment(acc[i][j], 0.f);

    issue_A(As[0], A, mBase, 0, DD, tid);
    issue_B(Bs[0], W, 0, cOff, DD, tid);
    CP_COMMIT();
    int buf = 0;
    for (int kt = 0; kt < 256; kt += 16) {
        CP_WAIT0();
        __syncthreads();
        if (kt + 16 < 256) {
            issue_A(As[buf ^ 1], A, mBase, kt + 16, DD, tid);
            issue_B(Bs[buf ^ 1], W, kt + 16, cOff, DD, tid);
            CP_COMMIT();
        }
        gemm_core(As[buf], Bs[buf], acc, wr, wc);
        buf ^= 1;
    }
    __syncthreads();   // reuse As as epilogue staging

    float* stg = (float*)As + warp * (16 * ST_LD);
    const int r = lane >> 1, c0 = (lane & 1) * 8;
#pragma unroll
    for (int i = 0; i < 4; i++)
#pragma unroll
        for (int j = 0; j < 2; j++) {
            wmma::store_matrix_sync(stg, acc[i][j], ST_LD, wmma::mem_row_major);
            __syncwarp();
            int gm = mBase + wr * 64 + i * 16 + r;
            int gc = cBase + wc * 32 + j * 16 + c0;
            int b = gm >> 11, n = gm & 2047;
#pragma unroll
            for (int u = 0; u < 8; u++) {
                float v = stg[r * ST_LD + c0 + u];
                int c = gc + u;
                if (c < 256) {
                    int h = c >> 6, d = c & 63;
                    g_qk[s][(((size_t)(b * HH + h) * NN + n) * DHH) + d] =
                        (v + b_qk[c]) * QKSCALE;
                } else {
                    int c2 = c - 256;
                    int h = c2 >> 6, d = c2 & 63;
                    g_v[s][(((size_t)(b * HH + h) * NN + n) * DHH) + d] = v + b_v[c2];
                }
            }
            __syncwarp();
        }
}

// ==========================================================================
// Kernel 2: attention (TF32, no-max softmax — sim entries are O(0.1)).
// grid (16, 16, 2) block 256.  cp.async double-buffered K/V.
// Dyn smem: Ks[2][64*72] | Vs[2][64*72] | Ps[128*72]
// ==========================================================================
#define AT_LD 72
#define ATTN_SMEM ((4 * 64 * AT_LD + 128 * AT_LD) * 4)

__global__ __launch_bounds__(256) void attn_kernel()
{
    extern __shared__ float sm[];
    float* Ks2 = sm;                       // 2 stages
    float* Vs2 = sm + 2 * 64 * AT_LD;      // 2 stages
    float* Ps  = sm + 4 * 64 * AT_LD;

    const int s  = blockIdx.z;
    const int bh = blockIdx.y;
    const int qb = blockIdx.x;
    const float* Q = g_qk[s]     + (size_t)bh * NN * DHH + (size_t)qb * 128 * DHH;
    const float* K = g_qk[s ^ 1] + (size_t)bh * NN * DHH;
    const float* V = g_v [s ^ 1] + (size_t)bh * NN * DHH;

    const int tid = threadIdx.x;
    const int w = tid >> 5;

    // stage Q into Ps
#pragma unroll
    for (int it = 0; it < 8; it++) {
        int i = tid + it * 256;
        int r = i >> 4, c4 = i & 15;
        *(float4*)(Ps + r * AT_LD + c4 * 4) = *(const float4*)(Q + r * 64 + c4 * 4);
    }

    // issue KV block 0
#pragma unroll
    for (int it = 0; it < 4; it++) {
        int i = tid + it * 256;
        int r = i >> 4, c4 = i & 15;
        cp16(Ks2 + r * AT_LD + c4 * 4, K + r * 64 + c4 * 4);
        cp16(Vs2 + r * AT_LD + c4 * 4, V + r * 64 + c4 * 4);
    }
    CP_COMMIT();

    __syncthreads();   // Q staged
    FragA qf[8];
#pragma unroll
    for (int kk = 0; kk < 8; kk++)
        wmma::load_matrix_sync(qf[kk], Ps + (w * 16) * AT_LD + kk * 8, AT_LD);

    FragC o[4];
#pragma unroll
    for (int c = 0; c < 4; c++) wmma::fill_fragment(o[c], 0.f);
    float lsum = 0.f;

    const int erow = tid >> 1;
    const int ecb  = (tid & 1) * 32;
    int buf = 0;

    for (int kb = 0; kb < NN / 64; kb++) {
        CP_WAIT0();
        __syncthreads();   // KV stage ready; also fences qf loads / prev-iter reads
        if (kb + 1 < NN / 64) {
            const float* Kb = K + (size_t)(kb + 1) * 64 * 64;
            const float* Vb = V + (size_t)(kb + 1) * 64 * 64;
            float* Kd = Ks2 + (buf ^ 1) * 64 * AT_LD;
            float* Vd = Vs2 + (buf ^ 1) * 64 * AT_LD;
#pragma unroll
            for (int it = 0; it < 4; it++) {
                int i = tid + it * 256;
                int r = i >> 4, c4 = i & 15;
                cp16(Kd + r * AT_LD + c4 * 4, Kb + r * 64 + c4 * 4);
                cp16(Vd + r * AT_LD + c4 * 4, Vb + r * 64 + c4 * 4);
            }
            CP_COMMIT();
        }
        const float* Ksb = Ks2 + buf * 64 * AT_LD;
        const float* Vsb = Vs2 + buf * 64 * AT_LD;

        // S = Q @ K^T (per warp 16x64)
        FragC sa[4];
#pragma unroll
        for (int c = 0; c < 4; c++) wmma::fill_fragment(sa[c], 0.f);
#pragma unroll
        for (int kk = 0; kk < 8; kk++) {
#pragma unroll
            for (int c = 0; c < 4; c++) {
                FragBc bf;
                wmma::load_matrix_sync(bf, Ksb + (c * 16) * AT_LD + kk * 8, AT_LD);
                wmma::mma_sync(sa[c], qf[kk], bf, sa[c]);
            }
        }
#pragma unroll
        for (int c = 0; c < 4; c++)
            wmma::store_matrix_sync(Ps + (w * 16) * AT_LD + c * 16, sa[c], AT_LD,
                                    wmma::mem_row_major);
        __syncthreads();

        // P = exp(S), partial sums
        {
            float rs = 0.f;
#pragma unroll
            for (int c = 0; c < 32; c++) {
                float p = __expf(Ps[erow * AT_LD + ecb + c]);
                Ps[erow * AT_LD + ecb + c] = p;
                rs += p;
            }
            rs += __shfl_xor_sync(0xffffffffu, rs, 1);
            lsum += rs;
        }
        __syncthreads();

        // O += P @ V
#pragma unroll
        for (int kk = 0; kk < 8; kk++) {
            FragA af;
            wmma::load_matrix_sync(af, Ps + (w * 16) * AT_LD + kk * 8, AT_LD);
#pragma unroll
            for (int c = 0; c < 4; c++) {
                FragB bf;
                wmma::load_matrix_sync(bf, Vsb + (kk * 8) * AT_LD + c * 16, AT_LD);
                wmma::mma_sync(o[c], af, bf, o[c]);
            }
        }
        buf ^= 1;
    }

    // finalize
    __syncthreads();
#pragma unroll
    for (int c = 0; c < 4; c++)
        wmma::store_matrix_sync(Ps + (w * 16) * AT_LD + c * 16, o[c], AT_LD,
                                wmma::mem_row_major);
    __syncthreads();

    const int b = bh >> 2, h = bh & 3;
    {
        float inv = 1.f / lsum;
        int n = qb * 128 + erow;
        float* dst = g_att[s] + ((size_t)(b * NN + n)) * DD + h * 64 + ecb;
        const float* src = Ps + erow * AT_LD + ecb;
#pragma unroll
        for (int c4 = 0; c4 < 8; c4++) {
            float4 v = *(const float4*)(src + c4 * 4);
            v.x *= inv; v.y *= inv; v.z *= inv; v.w *= inv;
            *(float4*)(dst + c4 * 4) = v;
        }
    }
}

// ==========================================================================
// Kernel 3: out projection. grid (2, 64, 2) block 256
// ==========================================================================
__global__ __launch_bounds__(256) void outproj_kernel(
    const float* __restrict__ w, const float* __restrict__ bias)
{
    __shared__ float As[2][128 * AS_LD];
    __shared__ float Bs[2][16 * BS_LD];

    const int s = blockIdx.z;
    const float* A = g_att[s];
    const int mBase = blockIdx.y * 128;
    const int cBase = blockIdx.x * 128;
    const int tid = threadIdx.x;
    const int warp = tid >> 5, lane = tid & 31;
    const int wr = warp >> 2, wc = warp & 3;

    FragC acc[4][2];
#pragma unroll
    for (int i = 0; i < 4; i++)
#pragma unroll
        for (int j = 0; j < 2; j++) wmma::fill_fragment(acc[i][j], 0.f);

    issue_A(As[0], A, mBase, 0, DD, tid);
    issue_B(Bs[0], w, 0, cBase, DD, tid);
    CP_COMMIT();
    int buf = 0;
    for (int kt = 0; kt < 256; kt += 16) {
        CP_WAIT0();
        __syncthreads();
        if (kt + 16 < 256) {
            issue_A(As[buf ^ 1], A, mBase, kt + 16, DD, tid);
            issue_B(Bs[buf ^ 1], w, kt + 16, cBase, DD, tid);
            CP_COMMIT();
        }
        gemm_core(As[buf], Bs[buf], acc, wr, wc);
        buf ^= 1;
    }
    __syncthreads();

    float* stg = (float*)As + warp * (16 * ST_LD);
    const int r = lane >> 1, c0 = (lane & 1) * 8;
#pragma unroll
    for (int i = 0; i < 4; i++)
#pragma unroll
        for (int j = 0; j < 2; j++) {
            wmma::store_matrix_sync(stg, acc[i][j], ST_LD, wmma::mem_row_major);
            __syncwarp();
            int gm = mBase + wr * 64 + i * 16 + r;
            int gc = cBase + wc * 32 + j * 16 + c0;
            float4 b0 = *(const float4*)(bias + gc);
            float4 b1 = *(const float4*)(bias + gc + 4);
            const float* sp = stg + r * ST_LD + c0;
            float4 v0 = make_float4(sp[0] + b0.x, sp[1] + b0.y, sp[2] + b0.z, sp[3] + b0.w);
            float4 v1 = make_float4(sp[4] + b1.x, sp[5] + b1.y, sp[6] + b1.z, sp[7] + b1.w);
            *(float4*)(&g_m[s][(size_t)gm * DD + gc])     = v0;
            *(float4*)(&g_m[s][(size_t)gm * DD + gc + 4]) = v1;
            __syncwarp();
        }
}

// ==========================================================================
// Kernel 4: FFN1.  h = [x | m] @ w_f1 + b_f1  (K=512). grid (4, 64, 2)
// ==========================================================================
__global__ __launch_bounds__(256) void ffn1_kernel(
    const float* __restrict__ x0, const float* __restrict__ x1,
    const float* __restrict__ w, const float* __restrict__ bias)
{
    __shared__ float As[2][128 * AS_LD];
    __shared__ float Bs[2][16 * BS_LD];

    const int s = blockIdx.z;
    const float* X  = s ? x1 : x0;
    const float* Mm = g_m[s];
    const int mBase = blockIdx.y * 128;
    const int cBase = blockIdx.x * 128;
    const int tid = threadIdx.x;
    const int warp = tid >> 5, lane = tid & 31;
    const int wr = warp >> 2, wc = warp & 3;

    FragC acc[4][2];
#pragma unroll
    for (int i = 0; i < 4; i++)
#pragma unroll
        for (int j = 0; j < 2; j++) wmma::fill_fragment(acc[i][j], 0.f);

    issue_A(As[0], X, mBase, 0, DD, tid);
    issue_B(Bs[0], w, 0, cBase, 2 * DD, tid);
    CP_COMMIT();
    int buf = 0;
    for (int kt = 0; kt < 512; kt += 16) {
        CP_WAIT0();
        __syncthreads();
        if (kt + 16 < 512) {
            int kn = kt + 16;
            const float* Asrc = (kn < 256) ? X : Mm;
            int kOff = (kn < 256) ? kn : kn - 256;
            issue_A(As[buf ^ 1], Asrc, mBase, kOff, DD, tid);
            issue_B(Bs[buf ^ 1], w, kn, cBase, 2 * DD, tid);
            CP_COMMIT();
        }
        gemm_core(As[buf], Bs[buf], acc, wr, wc);
        buf ^= 1;
    }
    __syncthreads();

    float* stg = (float*)As + warp * (16 * ST_LD);
    const int r = lane >> 1, c0 = (lane & 1) * 8;
#pragma unroll
    for (int i = 0; i < 4; i++)
#pragma unroll
        for (int j = 0; j < 2; j++) {
            wmma::store_matrix_sync(stg, acc[i][j], ST_LD, wmma::mem_row_major);
            __syncwarp();
            int gm = mBase + wr * 64 + i * 16 + r;
            int gc = cBase + wc * 32 + j * 16 + c0;
            float4 b0 = *(const float4*)(bias + gc);
            float4 b1 = *(const float4*)(bias + gc + 4);
            const float* sp = stg + r * ST_LD + c0;
            float4 v0 = make_float4(sp[0] + b0.x, sp[1] + b0.y, sp[2] + b0.z, sp[3] + b0.w);
            float4 v1 = make_float4(sp[4] + b1.x, sp[5] + b1.y, sp[6] + b1.z, sp[7] + b1.w);
            *(float4*)(&g_h[s][(size_t)gm * (2 * DD) + gc])     = v0;
            *(float4*)(&g_h[s][(size_t)gm * (2 * DD) + gc + 4]) = v1;
            __syncwarp();
        }
}

// ==========================================================================
// Kernel 5: LayerNorm(512) + exact GELU, in place. grid 16384 block 128
// ==========================================================================
__global__ __launch_bounds__(128) void ln_gelu_kernel(
    const float* __restrict__ g, const float* __restrict__ bta)
{
    const int row = blockIdx.x;
    const int s = row >> 13;
    float* h = g_h[s] + (size_t)(row & 8191) * 512;
    const int tid = threadIdx.x;

    float4 t = reinterpret_cast<float4*>(h)[tid];
    float sum = t.x + t.y + t.z + t.w;
    float sq  = t.x * t.x + t.y * t.y + t.z * t.z + t.w * t.w;
#pragma unroll
    for (int off = 16; off > 0; off >>= 1) {
        sum += __shfl_xor_sync(0xffffffffu, sum, off);
        sq  += __shfl_xor_sync(0xffffffffu, sq,  off);
    }
    __shared__ float ssum[4], ssq[4];
    const int w = tid >> 5;
    if ((tid & 31) == 0) { ssum[w] = sum; ssq[w] = sq; }
    __syncthreads();
    sum = ssum[0] + ssum[1] + ssum[2] + ssum[3];
    sq  = ssq[0]  + ssq[1]  + ssq[2]  + ssq[3];

    const float mu   = sum * (1.f / 512.f);
    const float var  = sq * (1.f / 512.f) - mu * mu;
    const float rstd = rsqrtf(var + 1e-5f);

    float4 gg = reinterpret_cast<const float4*>(g)[tid];
    float4 bb = reinterpret_cast<const float4*>(bta)[tid];
    auto act = [&](float v, float gv, float bv) {
        float y = (v - mu) * rstd * gv + bv;
        return 0.5f * y * (1.f + erff(y * 0.70710678118654752f));
    };
    t.x = act(t.x, gg.x, bb.x);
    t.y = act(t.y, gg.y, bb.y);
    t.z = act(t.z, gg.z, bb.z);
    t.w = act(t.w, gg.w, bb.w);
    reinterpret_cast<float4*>(h)[tid] = t;
}

// ==========================================================================
// Kernel 6: FFN2 + residual.  out = x + h @ w_f2 + b_f2 (K=512). grid (2,64,2)
// ==========================================================================
__global__ __launch_bounds__(256) void ffn2_kernel(
    const float* __restrict__ x0, const float* __restrict__ x1,
    const float* __restrict__ w, const float* __restrict__ bias,
    float* __restrict__ out)
{
    __shared__ float As[2][128 * AS_LD];
    __shared__ float Bs[2][16 * BS_LD];

    const int s = blockIdx.z;
    const float* X = s ? x1 : x0;
    const float* A = g_h[s];
    const int mBase = blockIdx.y * 128;
    const int cBase = blockIdx.x * 128;
    const int tid = threadIdx.x;
    const int warp = tid >> 5, lane = tid & 31;
    const int wr = warp >> 2, wc = warp & 3;

    FragC acc[4][2];
#pragma unroll
    for (int i = 0; i < 4; i++)
#pragma unroll
        for (int j = 0; j < 2; j++) wmma::fill_fragment(acc[i][j], 0.f);

    issue_A(As[0], A, mBase, 0, 2 * DD, tid);
    issue_B(Bs[0], w, 0, cBase, DD, tid);
    CP_COMMIT();
    int buf = 0;
    for (int kt = 0; kt < 512; kt += 16) {
        CP_WAIT0();
        __syncthreads();
        if (kt + 16 < 512) {
            issue_A(As[buf ^ 1], A, mBase, kt + 16, 2 * DD, tid);
            issue_B(Bs[buf ^ 1], w, kt + 16, cBase, DD, tid);
            CP_COMMIT();
        }
        gemm_core(As[buf], Bs[buf], acc, wr, wc);
        buf ^= 1;
    }
    __syncthreads();

    float* stg = (float*)As + warp * (16 * ST_LD);
    const int r = lane >> 1, c0 = (lane & 1) * 8;
#pragma unroll
    for (int i = 0; i < 4; i++)
#pragma unroll
        for (int j = 0; j < 2; j++) {
            wmma::store_matrix_sync(stg, acc[i][j], ST_LD, wmma::mem_row_major);
            __syncwarp();
            int gm = mBase + wr * 64 + i * 16 + r;
            int gc = cBase + wc * 32 + j * 16 + c0;
            float4 b0 = *(const float4*)(bias + gc);
            float4 b1 = *(const float4*)(bias + gc + 4);
            float4 x0v = *(const float4*)(X + (size_t)gm * DD + gc);
            float4 x1v = *(const float4*)(X + (size_t)gm * DD + gc + 4);
            const float* sp = stg + r * ST_LD + c0;
            float4 v0 = make_float4(sp[0] + b0.x + x0v.x, sp[1] + b0.y + x0v.y,
                                    sp[2] + b0.z + x0v.z, sp[3] + b0.w + x0v.w);
            float4 v1 = make_float4(sp[4] + b1.x + x1v.x, sp[5] + b1.y + x1v.y,
                                    sp[6] + b1.z + x1v.z, sp[7] + b1.w + x1v.w);
            *(float4*)(out + (size_t)s * MTOT * DD + (size_t)gm * DD + gc)     = v0;
            *(float4*)(out + (size_t)s * MTOT * DD + (size_t)gm * DD + gc + 4) = v1;
            __syncwarp();
        }
}

// ==========================================================================
extern "C" void kernel_launch(void* const* d_in, const int* in_sizes, int n_in,
                              void* d_out, int out_size)
{
    const float* x0    = (const float*)d_in[0];
    const float* x1    = (const float*)d_in[1];
    const float* w_qk  = (const float*)d_in[2];
    const float* b_qk  = (const float*)d_in[3];
    const float* w_v   = (const float*)d_in[4];
    const float* b_v   = (const float*)d_in[5];
    const float* w_out = (const float*)d_in[6];
    const float* b_out = (const float*)d_in[7];
    const float* w_f1  = (const float*)d_in[8];
    const float* b_f1  = (const float*)d_in[9];
    const float* ln_g  = (const float*)d_in[10];
    const float* ln_b  = (const float*)d_in[11];
    const float* w_f2  = (const float*)d_in[12];
    const float* b_f2  = (const float*)d_in[13];
    float* out = (float*)d_out;

    cudaFuncSetAttribute(attn_kernel,
                         cudaFuncAttributeMaxDynamicSharedMemorySize, ATTN_SMEM);

    qkv_kernel    <<<dim3(4, 64, 2), 256>>>(x0, x1, w_qk, b_qk, w_v, b_v);
    attn_kernel   <<<dim3(16, 16, 2), 256, ATTN_SMEM>>>();
    outproj_kernel<<<dim3(2, 64, 2), 256>>>(w_out, b_out);
    ffn1_kernel   <<<dim3(4, 64, 2), 256>>>(x0, x1, w_f1, b_f1);
    ln_gelu_kernel<<<16384, 128>>>(ln_g, ln_b);
    ffn2_kernel   <<<dim3(2, 64, 2), 256>>>(x0, x1, w_f2, b_f2, out);
}

// round 7
// speedup vs baseline: 1.2548x; 1.0124x over previous
#include <cuda_runtime.h>
#include <mma.h>
#include <math.h>

using namespace nvcuda;

// Problem constants
#define BB    4
#define NN    2048
#define DD    256
#define HH    4
#define DHH   64
#define BH    16
#define MTOT  8192
#define QKSCALE 0.35355339059327379f  // 64^{-0.25}

// -------- scratch ----------
__device__ float g_qk[2][BH * NN * DHH];
__device__ float g_v [2][BH * NN * DHH];
__device__ float g_att[2][MTOT * DD];
__device__ float g_m [2][MTOT * DD];
__device__ float g_h [2][MTOT * 2 * DD];

using FragA  = wmma::fragment<wmma::matrix_a, 16, 16, 8, wmma::precision::tf32, wmma::row_major>;
using FragB  = wmma::fragment<wmma::matrix_b, 16, 16, 8, wmma::precision::tf32, wmma::row_major>;
using FragBc = wmma::fragment<wmma::matrix_b, 16, 16, 8, wmma::precision::tf32, wmma::col_major>;
using FragC  = wmma::fragment<wmma::accumulator, 16, 16, 8, float>;

// ---- cp.async helpers ----
__device__ __forceinline__ void cp16(float* smem_dst, const float* gsrc) {
    unsigned int s = (unsigned int)__cvta_generic_to_shared(smem_dst);
    asm volatile("cp.async.cg.shared.global [%0], [%1], 16;" :: "r"(s), "l"(gsrc));
}
#define CP_COMMIT() asm volatile("cp.async.commit_group;")
#define CP_WAIT0()  asm volatile("cp.async.wait_group 0;")

// ==========================================================================
// TF32 GEMM block: BM=128, BN=128, BK=16, 256 thr = 8 warps (2x4),
// warp tile 64x32.  2-stage cp.async pipeline, ONE __syncthreads per K-step.
// ==========================================================================
#define AS_LD 24
#define BS_LD 136
#define ST_LD 20

__device__ __forceinline__ void gemm_core(const float* As, const float* Bs,
                                          FragC acc[4][2], int wr, int wc)
{
#pragma unroll
    for (int kk = 0; kk < 2; kk++) {
        FragA af[4];
        FragB bf[2];
#pragma unroll
        for (int i = 0; i < 4; i++)
            wmma::load_matrix_sync(af[i], As + (wr * 64 + i * 16) * AS_LD + kk * 8, AS_LD);
#pragma unroll
        for (int j = 0; j < 2; j++)
            wmma::load_matrix_sync(bf[j], Bs + (kk * 8) * BS_LD + wc * 32 + j * 16, BS_LD);
#pragma unroll
        for (int i = 0; i < 4; i++)
#pragma unroll
            for (int j = 0; j < 2; j++)
                wmma::mma_sync(acc[i][j], af[i], bf[j], acc[i][j]);
    }
}

__device__ __forceinline__ void issue_A(float* As, const float* A, int mBase,
                                        int kt, int lda, int tid)
{
#pragma unroll
    for (int it = 0; it < 2; it++) {
        int i = tid + it * 256;
        int row = i >> 2, c4 = i & 3;
        cp16(As + row * AS_LD + c4 * 4, A + (size_t)(mBase + row) * lda + kt + c4 * 4);
    }
}
__device__ __forceinline__ void issue_B(float* Bs, const float* B, int kt,
                                        int cOff, int ldb, int tid)
{
#pragma unroll
    for (int it = 0; it < 2; it++) {
        int i = tid + it * 256;
        int k = i >> 5, c4 = i & 31;
        cp16(Bs + k * BS_LD + c4 * 4, B + (size_t)(kt + k) * ldb + cOff + c4 * 4);
    }
}

// ==========================================================================
// Kernel 1: fused QK/V projection. grid (4, 64, 2) block 256
// ==========================================================================
__global__ __launch_bounds__(256) void qkv_kernel(
    const float* __restrict__ x0, const float* __restrict__ x1,
    const float* __restrict__ w_qk, const float* __restrict__ b_qk,
    const float* __restrict__ w_v,  const float* __restrict__ b_v)
{
    __shared__ float As[2][128 * AS_LD];
    __shared__ float Bs[2][16 * BS_LD];

    const int s = blockIdx.z;
    const float* A = s ? x1 : x0;
    const int mBase = blockIdx.y * 128;
    const int cBase = blockIdx.x * 128;
    const int tid = threadIdx.x;
    const int warp = tid >> 5, lane = tid & 31;
    const int wr = warp >> 2, wc = warp & 3;

    const float* W; int cOff;
    if (cBase < 256) { W = w_qk; cOff = cBase; }
    else             { W = w_v;  cOff = cBase - 256; }

    FragC acc[4][2];
#pragma unroll
    for (int i = 0; i < 4; i++)
#pragma unroll
        for (int j = 0; j < 2; j++) wmma::fill_fragment(acc[i][j], 0.f);

    issue_A(As[0], A, mBase, 0, DD, tid);
    issue_B(Bs[0], W, 0, cOff, DD, tid);
    CP_COMMIT();
    int buf = 0;
    for (int kt = 0; kt < 256; kt += 16) {
        CP_WAIT0();
        __syncthreads();
        if (kt + 16 < 256) {
            issue_A(As[buf ^ 1], A, mBase, kt + 16, DD, tid);
            issue_B(Bs[buf ^ 1], W, kt + 16, cOff, DD, tid);
            CP_COMMIT();
        }
        gemm_core(As[buf], Bs[buf], acc, wr, wc);
        buf ^= 1;
    }
    __syncthreads();   // reuse As as epilogue staging

    float* stg = (float*)As + warp * (16 * ST_LD);
    const int r = lane >> 1, c0 = (lane & 1) * 8;
#pragma unroll
    for (int i = 0; i < 4; i++)
#pragma unroll
        for (int j = 0; j < 2; j++) {
            wmma::store_matrix_sync(stg, acc[i][j], ST_LD, wmma::mem_row_major);
            __syncwarp();
            int gm = mBase + wr * 64 + i * 16 + r;
            int gc = cBase + wc * 32 + j * 16 + c0;
            int b = gm >> 11, n = gm & 2047;
#pragma unroll
            for (int u = 0; u < 8; u++) {
                float v = stg[r * ST_LD + c0 + u];
                int c = gc + u;
                if (c < 256) {
                    int h = c >> 6, d = c & 63;
                    g_qk[s][(((size_t)(b * HH + h) * NN + n) * DHH) + d] =
                        (v + b_qk[c]) * QKSCALE;
                } else {
                    int c2 = c - 256;
                    int h = c2 >> 6, d = c2 & 63;
                    g_v[s][(((size_t)(b * HH + h) * NN + n) * DHH) + d] = v + b_v[c2];
                }
            }
            __syncwarp();
        }
}

// ==========================================================================
// Kernel 2: attention (TF32, no-max softmax — sim entries are O(0.1)).
// grid (16, 16, 2) block 256.  cp.async double-buffered K/V.
// PER-WARP ROW OWNERSHIP of Ps: the whole S->exp->O chain runs with only
// __syncwarp(); the single __syncthreads per iteration publishes K/V.
// Dyn smem: Ks[2][64*72] | Vs[2][64*72] | Ps[128*72]
// ==========================================================================
#define AT_LD 72
#define ATTN_SMEM ((4 * 64 * AT_LD + 128 * AT_LD) * 4)

__global__ __launch_bounds__(256) void attn_kernel()
{
    extern __shared__ float sm[];
    float* Ks2 = sm;                       // 2 stages
    float* Vs2 = sm + 2 * 64 * AT_LD;      // 2 stages
    float* Ps  = sm + 4 * 64 * AT_LD;

    const int s  = blockIdx.z;
    const int bh = blockIdx.y;
    const int qb = blockIdx.x;
    const float* Q = g_qk[s]     + (size_t)bh * NN * DHH + (size_t)qb * 128 * DHH;
    const float* K = g_qk[s ^ 1] + (size_t)bh * NN * DHH;
    const float* V = g_v [s ^ 1] + (size_t)bh * NN * DHH;

    const int tid = threadIdx.x;
    const int w = tid >> 5;
    const int lane = tid & 31;

    // this thread's exp/output row (within the warp's 16-row tile)
    const int myrow = w * 16 + (lane >> 1);       // Ps row this thread processes
    const int ecb   = (lane & 1) * 32;            // col base (32 cols per thread)
    float* myP = Ps + myrow * AT_LD;

    // stage Q into Ps
#pragma unroll
    for (int it = 0; it < 8; it++) {
        int i = tid + it * 256;
        int r = i >> 4, c4 = i & 15;
        *(float4*)(Ps + r * AT_LD + c4 * 4) = *(const float4*)(Q + r * 64 + c4 * 4);
    }

    // issue KV block 0
#pragma unroll
    for (int it = 0; it < 4; it++) {
        int i = tid + it * 256;
        int r = i >> 4, c4 = i & 15;
        cp16(Ks2 + r * AT_LD + c4 * 4, K + r * 64 + c4 * 4);
        cp16(Vs2 + r * AT_LD + c4 * 4, V + r * 64 + c4 * 4);
    }
    CP_COMMIT();

    __syncthreads();   // Q staged (cross-warp: staging was block-distributed)
    FragA qf[8];
#pragma unroll
    for (int kk = 0; kk < 8; kk++)
        wmma::load_matrix_sync(qf[kk], Ps + (w * 16) * AT_LD + kk * 8, AT_LD);

    FragC o[4];
#pragma unroll
    for (int c = 0; c < 4; c++) wmma::fill_fragment(o[c], 0.f);
    float lsum = 0.f;
    int buf = 0;

    for (int kb = 0; kb < NN / 64; kb++) {
        CP_WAIT0();
        __syncthreads();   // K/V stage published; prev iter's K/V reads done
        if (kb + 1 < NN / 64) {
            const float* Kb = K + (size_t)(kb + 1) * 64 * 64;
            const float* Vb = V + (size_t)(kb + 1) * 64 * 64;
            float* Kd = Ks2 + (buf ^ 1) * 64 * AT_LD;
            float* Vd = Vs2 + (buf ^ 1) * 64 * AT_LD;
#pragma unroll
            for (int it = 0; it < 4; it++) {
                int i = tid + it * 256;
                int r = i >> 4, c4 = i & 15;
                cp16(Kd + r * AT_LD + c4 * 4, Kb + r * 64 + c4 * 4);
                cp16(Vd + r * AT_LD + c4 * 4, Vb + r * 64 + c4 * 4);
            }
            CP_COMMIT();
        }
        const float* Ksb = Ks2 + buf * 64 * AT_LD;
        const float* Vsb = Vs2 + buf * 64 * AT_LD;

        // S = Q @ K^T (per warp 16x64)
        FragC sa[4];
#pragma unroll
        for (int c = 0; c < 4; c++) wmma::fill_fragment(sa[c], 0.f);
#pragma unroll
        for (int kk = 0; kk < 8; kk++) {
#pragma unroll
            for (int c = 0; c < 4; c++) {
                FragBc bf;
                wmma::load_matrix_sync(bf, Ksb + (c * 16) * AT_LD + kk * 8, AT_LD);
                wmma::mma_sync(sa[c], qf[kk], bf, sa[c]);
            }
        }
        // store S to OWN rows
#pragma unroll
        for (int c = 0; c < 4; c++)
            wmma::store_matrix_sync(Ps + (w * 16) * AT_LD + c * 16, sa[c], AT_LD,
                                    wmma::mem_row_major);
        __syncwarp();

        // exp on OWN rows (2 lanes per row, 32 cols each), row-sum via shfl
        {
            float rs = 0.f;
#pragma unroll
            for (int c = 0; c < 32; c++) {
                float p = __expf(myP[ecb + c]);
                myP[ecb + c] = p;
                rs += p;
            }
            rs += __shfl_xor_sync(0xffffffffu, rs, 1);
            lsum += rs;
        }
        __syncwarp();

        // O += P @ V  (reads OWN P rows + shared V tile)
#pragma unroll
        for (int kk = 0; kk < 8; kk++) {
            FragA af;
            wmma::load_matrix_sync(af, Ps + (w * 16) * AT_LD + kk * 8, AT_LD);
#pragma unroll
            for (int c = 0; c < 4; c++) {
                FragB bf;
                wmma::load_matrix_sync(bf, Vsb + (kk * 8) * AT_LD + c * 16, AT_LD);
                wmma::mma_sync(o[c], af, bf, o[c]);
            }
        }
        buf ^= 1;
    }

    // finalize: stage O to OWN rows, normalize with in-register row sum
#pragma unroll
    for (int c = 0; c < 4; c++)
        wmma::store_matrix_sync(Ps + (w * 16) * AT_LD + c * 16, o[c], AT_LD,
                                wmma::mem_row_major);
    __syncwarp();

    const int b = bh >> 2, h = bh & 3;
    {
        float inv = 1.f / lsum;
        int n = qb * 128 + myrow;
        float* dst = g_att[s] + ((size_t)(b * NN + n)) * DD + h * 64 + ecb;
        const float* src = myP + ecb;
#pragma unroll
        for (int c4 = 0; c4 < 8; c4++) {
            float4 v = *(const float4*)(src + c4 * 4);
            v.x *= inv; v.y *= inv; v.z *= inv; v.w *= inv;
            *(float4*)(dst + c4 * 4) = v;
        }
    }
}

// ==========================================================================
// Kernel 3: out projection. grid (2, 64, 2) block 256
// ==========================================================================
__global__ __launch_bounds__(256) void outproj_kernel(
    const float* __restrict__ w, const float* __restrict__ bias)
{
    __shared__ float As[2][128 * AS_LD];
    __shared__ float Bs[2][16 * BS_LD];

    const int s = blockIdx.z;
    const float* A = g_att[s];
    const int mBase = blockIdx.y * 128;
    const int cBase = blockIdx.x * 128;
    const int tid = threadIdx.x;
    const int warp = tid >> 5, lane = tid & 31;
    const int wr = warp >> 2, wc = warp & 3;

    FragC acc[4][2];
#pragma unroll
    for (int i = 0; i < 4; i++)
#pragma unroll
        for (int j = 0; j < 2; j++) wmma::fill_fragment(acc[i][j], 0.f);

    issue_A(As[0], A, mBase, 0, DD, tid);
    issue_B(Bs[0], w, 0, cBase, DD, tid);
    CP_COMMIT();
    int buf = 0;
    for (int kt = 0; kt < 256; kt += 16) {
        CP_WAIT0();
        __syncthreads();
        if (kt + 16 < 256) {
            issue_A(As[buf ^ 1], A, mBase, kt + 16, DD, tid);
            issue_B(Bs[buf ^ 1], w, kt + 16, cBase, DD, tid);
            CP_COMMIT();
        }
        gemm_core(As[buf], Bs[buf], acc, wr, wc);
        buf ^= 1;
    }
    __syncthreads();

    float* stg = (float*)As + warp * (16 * ST_LD);
    const int r = lane >> 1, c0 = (lane & 1) * 8;
#pragma unroll
    for (int i = 0; i < 4; i++)
#pragma unroll
        for (int j = 0; j < 2; j++) {
            wmma::store_matrix_sync(stg, acc[i][j], ST_LD, wmma::mem_row_major);
            __syncwarp();
            int gm = mBase + wr * 64 + i * 16 + r;
            int gc = cBase + wc * 32 + j * 16 + c0;
            float4 b0 = *(const float4*)(bias + gc);
            float4 b1 = *(const float4*)(bias + gc + 4);
            const float* sp = stg + r * ST_LD + c0;
            float4 v0 = make_float4(sp[0] + b0.x, sp[1] + b0.y, sp[2] + b0.z, sp[3] + b0.w);
            float4 v1 = make_float4(sp[4] + b1.x, sp[5] + b1.y, sp[6] + b1.z, sp[7] + b1.w);
            *(float4*)(&g_m[s][(size_t)gm * DD + gc])     = v0;
            *(float4*)(&g_m[s][(size_t)gm * DD + gc + 4]) = v1;
            __syncwarp();
        }
}

// ==========================================================================
// Kernel 4: FFN1.  h = [x | m] @ w_f1 + b_f1  (K=512). grid (4, 64, 2)
// ==========================================================================
__global__ __launch_bounds__(256) void ffn1_kernel(
    const float* __restrict__ x0, const float* __restrict__ x1,
    const float* __restrict__ w, const float* __restrict__ bias)
{
    __shared__ float As[2][128 * AS_LD];
    __shared__ float Bs[2][16 * BS_LD];

    const int s = blockIdx.z;
    const float* X  = s ? x1 : x0;
    const float* Mm = g_m[s];
    const int mBase = blockIdx.y * 128;
    const int cBase = blockIdx.x * 128;
    const int tid = threadIdx.x;
    const int warp = tid >> 5, lane = tid & 31;
    const int wr = warp >> 2, wc = warp & 3;

    FragC acc[4][2];
#pragma unroll
    for (int i = 0; i < 4; i++)
#pragma unroll
        for (int j = 0; j < 2; j++) wmma::fill_fragment(acc[i][j], 0.f);

    issue_A(As[0], X, mBase, 0, DD, tid);
    issue_B(Bs[0], w, 0, cBase, 2 * DD, tid);
    CP_COMMIT();
    int buf = 0;
    for (int kt = 0; kt < 512; kt += 16) {
        CP_WAIT0();
        __syncthreads();
        if (kt + 16 < 512) {
            int kn = kt + 16;
            const float* Asrc = (kn < 256) ? X : Mm;
            int kOff = (kn < 256) ? kn : kn - 256;
            issue_A(As[buf ^ 1], Asrc, mBase, kOff, DD, tid);
            issue_B(Bs[buf ^ 1], w, kn, cBase, 2 * DD, tid);
            CP_COMMIT();
        }
        gemm_core(As[buf], Bs[buf], acc, wr, wc);
        buf ^= 1;
    }
    __syncthreads();

    float* stg = (float*)As + warp * (16 * ST_LD);
    const int r = lane >> 1, c0 = (lane & 1) * 8;
#pragma unroll
    for (int i = 0; i < 4; i++)
#pragma unroll
        for (int j = 0; j < 2; j++) {
            wmma::store_matrix_sync(stg, acc[i][j], ST_LD, wmma::mem_row_major);
            __syncwarp();
            int gm = mBase + wr * 64 + i * 16 + r;
            int gc = cBase + wc * 32 + j * 16 + c0;
            float4 b0 = *(const float4*)(bias + gc);
            float4 b1 = *(const float4*)(bias + gc + 4);
            const float* sp = stg + r * ST_LD + c0;
            float4 v0 = make_float4(sp[0] + b0.x, sp[1] + b0.y, sp[2] + b0.z, sp[3] + b0.w);
            float4 v1 = make_float4(sp[4] + b1.x, sp[5] + b1.y, sp[6] + b1.z, sp[7] + b1.w);
            *(float4*)(&g_h[s][(size_t)gm * (2 * DD) + gc])     = v0;
            *(float4*)(&g_h[s][(size_t)gm * (2 * DD) + gc + 4]) = v1;
            __syncwarp();
        }
}

// ==========================================================================
// Kernel 5: LayerNorm(512) + exact GELU, in place. grid 16384 block 128
// ==========================================================================
__global__ __launch_bounds__(128) void ln_gelu_kernel(
    const float* __restrict__ g, const float* __restrict__ bta)
{
    const int row = blockIdx.x;
    const int s = row >> 13;
    float* h = g_h[s] + (size_t)(row & 8191) * 512;
    const int tid = threadIdx.x;

    float4 t = reinterpret_cast<float4*>(h)[tid];
    float sum = t.x + t.y + t.z + t.w;
    float sq  = t.x * t.x + t.y * t.y + t.z * t.z + t.w * t.w;
#pragma unroll
    for (int off = 16; off > 0; off >>= 1) {
        sum += __shfl_xor_sync(0xffffffffu, sum, off);
        sq  += __shfl_xor_sync(0xffffffffu, sq,  off);
    }
    __shared__ float ssum[4], ssq[4];
    const int w = tid >> 5;
    if ((tid & 31) == 0) { ssum[w] = sum; ssq[w] = sq; }
    __syncthreads();
    sum = ssum[0] + ssum[1] + ssum[2] + ssum[3];
    sq  = ssq[0]  + ssq[1]  + ssq[2]  + ssq[3];

    const float mu   = sum * (1.f / 512.f);
    const float var  = sq * (1.f / 512.f) - mu * mu;
    const float rstd = rsqrtf(var + 1e-5f);

    float4 gg = reinterpret_cast<const float4*>(g)[tid];
    float4 bb = reinterpret_cast<const float4*>(bta)[tid];
    auto act = [&](float v, float gv, float bv) {
        float y = (v - mu) * rstd * gv + bv;
        return 0.5f * y * (1.f + erff(y * 0.70710678118654752f));
    };
    t.x = act(t.x, gg.x, bb.x);
    t.y = act(t.y, gg.y, bb.y);
    t.z = act(t.z, gg.z, bb.z);
    t.w = act(t.w, gg.w, bb.w);
    reinterpret_cast<float4*>(h)[tid] = t;
}

// ==========================================================================
// Kernel 6: FFN2 + residual.  out = x + h @ w_f2 + b_f2 (K=512). grid (2,64,2)
// ==========================================================================
__global__ __launch_bounds__(256) void ffn2_kernel(
    const float* __restrict__ x0, const float* __restrict__ x1,
    const float* __restrict__ w, const float* __restrict__ bias,
    float* __restrict__ out)
{
    __shared__ float As[2][128 * AS_LD];
    __shared__ float Bs[2][16 * BS_LD];

    const int s = blockIdx.z;
    const float* X = s ? x1 : x0;
    const float* A = g_h[s];
    const int mBase = blockIdx.y * 128;
    const int cBase = blockIdx.x * 128;
    const int tid = threadIdx.x;
    const int warp = tid >> 5, lane = tid & 31;
    const int wr = warp >> 2, wc = warp & 3;

    FragC acc[4][2];
#pragma unroll
    for (int i = 0; i < 4; i++)
#pragma unroll
        for (int j = 0; j < 2; j++) wmma::fill_fragment(acc[i][j], 0.f);

    issue_A(As[0], A, mBase, 0, 2 * DD, tid);
    issue_B(Bs[0], w, 0, cBase, DD, tid);
    CP_COMMIT();
    int buf = 0;
    for (int kt = 0; kt < 512; kt += 16) {
        CP_WAIT0();
        __syncthreads();
        if (kt + 16 < 512) {
            issue_A(As[buf ^ 1], A, mBase, kt + 16, 2 * DD, tid);
            issue_B(Bs[buf ^ 1], w, kt + 16, cBase, DD, tid);
            CP_COMMIT();
        }
        gemm_core(As[buf], Bs[buf], acc, wr, wc);
        buf ^= 1;
    }
    __syncthreads();

    float* stg = (float*)As + warp * (16 * ST_LD);
    const int r = lane >> 1, c0 = (lane & 1) * 8;
#pragma unroll
    for (int i = 0; i < 4; i++)
#pragma unroll
        for (int j = 0; j < 2; j++) {
            wmma::store_matrix_sync(stg, acc[i][j], ST_LD, wmma::mem_row_major);
            __syncwarp();
            int gm = mBase + wr * 64 + i * 16 + r;
            int gc = cBase + wc * 32 + j * 16 + c0;
            float4 b0 = *(const float4*)(bias + gc);
            float4 b1 = *(const float4*)(bias + gc + 4);
            float4 x0v = *(const float4*)(X + (size_t)gm * DD + gc);
            float4 x1v = *(const float4*)(X + (size_t)gm * DD + gc + 4);
            const float* sp = stg + r * ST_LD + c0;
            float4 v0 = make_float4(sp[0] + b0.x + x0v.x, sp[1] + b0.y + x0v.y,
                                    sp[2] + b0.z + x0v.z, sp[3] + b0.w + x0v.w);
            float4 v1 = make_float4(sp[4] + b1.x + x1v.x, sp[5] + b1.y + x1v.y,
                                    sp[6] + b1.z + x1v.z, sp[7] + b1.w + x1v.w);
            *(float4*)(out + (size_t)s * MTOT * DD + (size_t)gm * DD + gc)     = v0;
            *(float4*)(out + (size_t)s * MTOT * DD + (size_t)gm * DD + gc + 4) = v1;
            __syncwarp();
        }
}

// ==========================================================================
extern "C" void kernel_launch(void* const* d_in, const int* in_sizes, int n_in,
                              void* d_out, int out_size)
{
    const float* x0    = (const float*)d_in[0];
    const float* x1    = (const float*)d_in[1];
    const float* w_qk  = (const float*)d_in[2];
    const float* b_qk  = (const float*)d_in[3];
    const float* w_v   = (const float*)d_in[4];
    const float* b_v   = (const float*)d_in[5];
    const float* w_out = (const float*)d_in[6];
    const float* b_out = (const float*)d_in[7];
    const float* w_f1  = (const float*)d_in[8];
    const float* b_f1  = (const float*)d_in[9];
    const float* ln_g  = (const float*)d_in[10];
    const float* ln_b  = (const float*)d_in[11];
    const float* w_f2  = (const float*)d_in[12];
    const float* b_f2  = (const float*)d_in[13];
    float* out = (float*)d_out;

    cudaFuncSetAttribute(attn_kernel,
                         cudaFuncAttributeMaxDynamicSharedMemorySize, ATTN_SMEM);

    qkv_kernel    <<<dim3(4, 64, 2), 256>>>(x0, x1, w_qk, b_qk, w_v, b_v);
    attn_kernel   <<<dim3(16, 16, 2), 256, ATTN_SMEM>>>();
    outproj_kernel<<<dim3(2, 64, 2), 256>>>(w_out, b_out);
    ffn1_kernel   <<<dim3(4, 64, 2), 256>>>(x0, x1, w_f1, b_f1);
    ln_gelu_kernel<<<16384, 128>>>(ln_g, ln_b);
    ffn2_kernel   <<<dim3(2, 64, 2), 256>>>(x0, x1, w_f2, b_f2, out);
}

// round 12
// speedup vs baseline: 3.1124x; 2.4803x over previous
#include <cuda_runtime.h>
#include <cuda_fp16.h>
#include <mma.h>
#include <math.h>

using namespace nvcuda;

// Problem constants
#define BB    4
#define NN    2048
#define DD    256
#define HH    4
#define DHH   64
#define BH    16
#define MTOT  8192
#define QKSCALE 0.35355339059327379f  // 64^{-0.25}

// -------- scratch (fp16 except g_h which feeds LayerNorm) ----------
__device__ __half g_xh [2][MTOT * DD];        // x0/x1 as half
__device__ __half g_wqk[DD * DD];
__device__ __half g_wv [DD * DD];
__device__ __half g_wout[DD * DD];
__device__ __half g_wf1[4 * DD * DD];         // 512x512
__device__ __half g_wf2[2 * DD * DD];         // 512x256
__device__ __half g_qk [2][BH * NN * DHH];
__device__ __half g_v  [2][BH * NN * DHH];
__device__ __half g_att[2][MTOT * DD];
__device__ __half g_m  [2][MTOT * DD];
__device__ float  g_h  [2][MTOT * 2 * DD];    // FFN hidden (f32 for LN)
__device__ __half g_hh [2][MTOT * 2 * DD];    // post-LN/GELU as half

using FragAh  = wmma::fragment<wmma::matrix_a, 16, 16, 16, __half, wmma::row_major>;
using FragBh  = wmma::fragment<wmma::matrix_b, 16, 16, 16, __half, wmma::row_major>;
using FragBcH = wmma::fragment<wmma::matrix_b, 16, 16, 16, __half, wmma::col_major>;
using FragC16 = wmma::fragment<wmma::accumulator, 16, 16, 16, float>;

// ---- cp.async helpers ----
__device__ __forceinline__ void cp16(void* smem_dst, const void* gsrc) {
    unsigned int s = (unsigned int)__cvta_generic_to_shared(smem_dst);
    asm volatile("cp.async.cg.shared.global [%0], [%1], 16;" :: "r"(s), "l"(gsrc));
}
#define CP_COMMIT() asm volatile("cp.async.commit_group;")
#define CP_WAIT0()  asm volatile("cp.async.wait_group 0;")

// ==========================================================================
// Kernel 0: f32 -> f16 conversion of inputs + weights (once per launch)
// grid (2048, 7) block 256, 4 elems/thread
// ==========================================================================
__global__ __launch_bounds__(256) void cvt_kernel(
    const float* __restrict__ x0, const float* __restrict__ x1,
    const float* __restrict__ wqk, const float* __restrict__ wv,
    const float* __restrict__ wout, const float* __restrict__ wf1,
    const float* __restrict__ wf2)
{
    const float* src; __half* dst; int n;
    switch (blockIdx.y) {
    case 0: src = x0;  dst = g_xh[0]; n = MTOT * DD;  break;
    case 1: src = x1;  dst = g_xh[1]; n = MTOT * DD;  break;
    case 2: src = wqk; dst = g_wqk;   n = DD * DD;    break;
    case 3: src = wv;  dst = g_wv;    n = DD * DD;    break;
    case 4: src = wout;dst = g_wout;  n = DD * DD;    break;
    case 5: src = wf1; dst = g_wf1;   n = 4 * DD * DD;break;
    default:src = wf2; dst = g_wf2;   n = 2 * DD * DD;break;
    }
    int idx = (blockIdx.x * 256 + threadIdx.x) * 4;
    if (idx < n) {
        float4 v = *(const float4*)(src + idx);
        *(__half2*)(dst + idx)     = __floats2half2_rn(v.x, v.y);
        *(__half2*)(dst + idx + 2) = __floats2half2_rn(v.z, v.w);
    }
}

// ==========================================================================
// FP16 GEMM block: BM=128, BN=128, BK=32, 256 thr = 8 warps (2x4),
// warp tile 64x32 (m16n16k16).  2-stage cp.async, one sync per K-step.
// ==========================================================================
#define ASH_LD 40    // halves (32 + 8 pad); 80B row, 16B multiple
#define BSH_LD 136   // halves; 272B row
#define ST_LD  20

__device__ __forceinline__ void gemm_core_h(const __half* As, const __half* Bs,
                                            FragC16 acc[4][2], int wr, int wc)
{
#pragma unroll
    for (int kk = 0; kk < 2; kk++) {
        FragAh af[4];
        FragBh bf[2];
#pragma unroll
        for (int i = 0; i < 4; i++)
            wmma::load_matrix_sync(af[i], As + (wr * 64 + i * 16) * ASH_LD + kk * 16, ASH_LD);
#pragma unroll
        for (int j = 0; j < 2; j++)
            wmma::load_matrix_sync(bf[j], Bs + (kk * 16) * BSH_LD + wc * 32 + j * 16, BSH_LD);
#pragma unroll
        for (int i = 0; i < 4; i++)
#pragma unroll
            for (int j = 0; j < 2; j++)
                wmma::mma_sync(acc[i][j], af[i], bf[j], acc[i][j]);
    }
}

// A tile 128x32 halves: 4 cp16 per row, 512 total -> 2/thread
__device__ __forceinline__ void issue_Ah(__half* As, const __half* A, int mBase,
                                         int kt, int lda, int tid)
{
#pragma unroll
    for (int it = 0; it < 2; it++) {
        int i = tid + it * 256;
        int row = i >> 2, c8 = i & 3;
        cp16(As + row * ASH_LD + c8 * 8,
             A + (size_t)(mBase + row) * lda + kt + c8 * 8);
    }
}
// B tile 32x128 halves: 16 cp16 per row, 512 total -> 2/thread
__device__ __forceinline__ void issue_Bh(__half* Bs, const __half* B, int kt,
                                         int cOff, int ldb, int tid)
{
#pragma unroll
    for (int it = 0; it < 2; it++) {
        int i = tid + it * 256;
        int k = i >> 4, c8 = i & 15;
        cp16(Bs + k * BSH_LD + c8 * 8,
             B + (size_t)(kt + k) * ldb + cOff + c8 * 8);
    }
}

// ==========================================================================
// Kernel 1: fused QK/V projection. grid (4, 64, 2) block 256
// ==========================================================================
__global__ __launch_bounds__(256) void qkv_kernel(
    const float* __restrict__ b_qk, const float* __restrict__ b_v)
{
    __shared__ __align__(16) __half As[2][128 * ASH_LD];
    __shared__ __align__(16) __half Bs[2][32 * BSH_LD];

    const int s = blockIdx.z;
    const __half* A = g_xh[s];
    const int mBase = blockIdx.y * 128;
    const int cBase = blockIdx.x * 128;
    const int tid = threadIdx.x;
    const int warp = tid >> 5, lane = tid & 31;
    const int wr = warp >> 2, wc = warp & 3;

    const __half* W; int cOff;
    if (cBase < 256) { W = g_wqk; cOff = cBase; }
    else             { W = g_wv;  cOff = cBase - 256; }

    FragC16 acc[4][2];
#pragma unroll
    for (int i = 0; i < 4; i++)
#pragma unroll
        for (int j = 0; j < 2; j++) wmma::fill_fragment(acc[i][j], 0.f);

    issue_Ah(As[0], A, mBase, 0, DD, tid);
    issue_Bh(Bs[0], W, 0, cOff, DD, tid);
    CP_COMMIT();
    int buf = 0;
    for (int kt = 0; kt < 256; kt += 32) {
        CP_WAIT0();
        __syncthreads();
        if (kt + 32 < 256) {
            issue_Ah(As[buf ^ 1], A, mBase, kt + 32, DD, tid);
            issue_Bh(Bs[buf ^ 1], W, kt + 32, cOff, DD, tid);
            CP_COMMIT();
        }
        gemm_core_h(As[buf], Bs[buf], acc, wr, wc);
        buf ^= 1;
    }
    __syncthreads();   // reuse As as epilogue staging (f32)

    float* stg = (float*)As + warp * (16 * ST_LD);
    const int r = lane >> 1, c0 = (lane & 1) * 8;
#pragma unroll
    for (int i = 0; i < 4; i++)
#pragma unroll
        for (int j = 0; j < 2; j++) {
            wmma::store_matrix_sync(stg, acc[i][j], ST_LD, wmma::mem_row_major);
            __syncwarp();
            int gm = mBase + wr * 64 + i * 16 + r;
            int gc = cBase + wc * 32 + j * 16 + c0;
            int b = gm >> 11, n = gm & 2047;
#pragma unroll
            for (int u = 0; u < 8; u++) {
                float v = stg[r * ST_LD + c0 + u];
                int c = gc + u;
                if (c < 256) {
                    int h = c >> 6, d = c & 63;
                    g_qk[s][(((size_t)(b * HH + h) * NN + n) * DHH) + d] =
                        __float2half_rn((v + b_qk[c]) * QKSCALE);
                } else {
                    int c2 = c - 256;
                    int h = c2 >> 6, d = c2 & 63;
                    g_v[s][(((size_t)(b * HH + h) * NN + n) * DHH) + d] =
                        __float2half_rn(v + b_v[c2]);
                }
            }
            __syncwarp();
        }
}

// ==========================================================================
// Kernel 2: attention (fp16 MMA, f32 S/exp, no-max softmax).
// grid (16, 16, 2) block 256.  cp.async double-buffered K/V, per-warp rows.
// Dyn smem bytes: Ks2 2x[64x72h] | Vs2 2x[64x72h] | Ps[128x72 f32] | Ph[128x72h]
// ==========================================================================
#define KV_LD 72
#define PS_LD 72
#define PH_LD 72
#define ATTN_SMEM (18432 + 18432 + 36864 + 18432)   // 92160

__global__ __launch_bounds__(256) void attn_kernel()
{
    extern __shared__ char smc[];
    __half* Ks2 = (__half*)smc;                   // 2 stages 64x72
    __half* Vs2 = (__half*)(smc + 18432);
    float*  Ps  = (float*) (smc + 36864);         // 128x72 f32
    __half* Ph  = (__half*)(smc + 73728);         // 128x72 half (Q, then P)

    const int s  = blockIdx.z;
    const int bh = blockIdx.y;
    const int qb = blockIdx.x;
    const __half* Q = g_qk[s]     + (size_t)bh * NN * DHH + (size_t)qb * 128 * DHH;
    const __half* K = g_qk[s ^ 1] + (size_t)bh * NN * DHH;
    const __half* V = g_v [s ^ 1] + (size_t)bh * NN * DHH;

    const int tid = threadIdx.x;
    const int w = tid >> 5;
    const int lane = tid & 31;
    const int myrow = w * 16 + (lane >> 1);
    const int ecb   = (lane & 1) * 32;

    // stage Q (128x64 halves, 8 cp16/row -> 4/thread) into Ph
#pragma unroll
    for (int it = 0; it < 4; it++) {
        int i = tid + it * 256;            // < 1024
        int r = i >> 3, c8 = i & 7;
        cp16(Ph + r * PH_LD + c8 * 8, Q + r * 64 + c8 * 8);
    }
    // issue KV block 0 (64x64 halves each, 8 cp16/row -> 2/thread each)
#pragma unroll
    for (int it = 0; it < 2; it++) {
        int i = tid + it * 256;            // < 512
        int r = i >> 3, c8 = i & 7;
        cp16(Ks2 + r * KV_LD + c8 * 8, K + r * 64 + c8 * 8);
        cp16(Vs2 + r * KV_LD + c8 * 8, V + r * 64 + c8 * 8);
    }
    CP_COMMIT();
    CP_WAIT0();
    __syncthreads();   // Q + KV0 staged

    FragAh qf[4];
#pragma unroll
    for (int kk = 0; kk < 4; kk++)
        wmma::load_matrix_sync(qf[kk], Ph + (w * 16) * PH_LD + kk * 16, PH_LD);

    FragC16 o[4];
#pragma unroll
    for (int c = 0; c < 4; c++) wmma::fill_fragment(o[c], 0.f);
    float lsum = 0.f;
    int buf = 0;

    for (int kb = 0; kb < NN / 64; kb++) {
        CP_WAIT0();
        __syncthreads();   // KV stage published; prev iter reads done
        if (kb + 1 < NN / 64) {
            const __half* Kb = K + (size_t)(kb + 1) * 64 * 64;
            const __half* Vb = V + (size_t)(kb + 1) * 64 * 64;
            __half* Kd = Ks2 + (buf ^ 1) * 64 * KV_LD;
            __half* Vd = Vs2 + (buf ^ 1) * 64 * KV_LD;
#pragma unroll
            for (int it = 0; it < 2; it++) {
                int i = tid + it * 256;
                int r = i >> 3, c8 = i & 7;
                cp16(Kd + r * KV_LD + c8 * 8, Kb + r * 64 + c8 * 8);
                cp16(Vd + r * KV_LD + c8 * 8, Vb + r * 64 + c8 * 8);
            }
            CP_COMMIT();
        }
        const __half* Ksb = Ks2 + buf * 64 * KV_LD;
        const __half* Vsb = Vs2 + buf * 64 * KV_LD;

        // S = Q @ K^T (per warp 16x64), f32 accum
        FragC16 sa[4];
#pragma unroll
        for (int c = 0; c < 4; c++) wmma::fill_fragment(sa[c], 0.f);
#pragma unroll
        for (int kk = 0; kk < 4; kk++) {
#pragma unroll
            for (int c = 0; c < 4; c++) {
                FragBcH bf;
                wmma::load_matrix_sync(bf, Ksb + (c * 16) * KV_LD + kk * 16, KV_LD);
                wmma::mma_sync(sa[c], qf[kk], bf, sa[c]);
            }
        }
#pragma unroll
        for (int c = 0; c < 4; c++)
            wmma::store_matrix_sync(Ps + (w * 16) * PS_LD + c * 16, sa[c], PS_LD,
                                    wmma::mem_row_major);
        __syncwarp();

        // exp on OWN rows (f32), write P as half, row-sum via shfl
        {
            float rs = 0.f;
            const float* sP = Ps + myrow * PS_LD + ecb;
            __half2* dP = (__half2*)(Ph + myrow * PH_LD + ecb);
#pragma unroll
            for (int c = 0; c < 32; c += 2) {
                float p0 = __expf(sP[c]);
                float p1 = __expf(sP[c + 1]);
                rs += p0 + p1;
                dP[c >> 1] = __floats2half2_rn(p0, p1);
            }
            rs += __shfl_xor_sync(0xffffffffu, rs, 1);
            lsum += rs;
        }
        __syncwarp();

        // O += P @ V  (own P rows + shared V tile)
#pragma unroll
        for (int kk = 0; kk < 4; kk++) {
            FragAh af;
            wmma::load_matrix_sync(af, Ph + (w * 16) * PH_LD + kk * 16, PH_LD);
#pragma unroll
            for (int c = 0; c < 4; c++) {
                FragBh bf;
                wmma::load_matrix_sync(bf, Vsb + (kk * 16) * KV_LD + c * 16, KV_LD);
                wmma::mma_sync(o[c], af, bf, o[c]);
            }
        }
        buf ^= 1;
    }

    // finalize: stage O (f32) to OWN rows, normalize, write half
#pragma unroll
    for (int c = 0; c < 4; c++)
        wmma::store_matrix_sync(Ps + (w * 16) * PS_LD + c * 16, o[c], PS_LD,
                                wmma::mem_row_major);
    __syncwarp();

    const int b = bh >> 2, h = bh & 3;
    {
        float inv = 1.f / lsum;
        int n = qb * 128 + myrow;
        __half* dst = g_att[s] + ((size_t)(b * NN + n)) * DD + h * 64 + ecb;
        const float* src = Ps + myrow * PS_LD + ecb;
#pragma unroll
        for (int c = 0; c < 32; c += 2)
            *(__half2*)(dst + c) = __floats2half2_rn(src[c] * inv, src[c + 1] * inv);
    }
}

// ==========================================================================
// Kernel 3: out projection. grid (2, 64, 2) block 256
// ==========================================================================
__global__ __launch_bounds__(256) void outproj_kernel(const float* __restrict__ bias)
{
    __shared__ __align__(16) __half As[2][128 * ASH_LD];
    __shared__ __align__(16) __half Bs[2][32 * BSH_LD];

    const int s = blockIdx.z;
    const __half* A = g_att[s];
    const int mBase = blockIdx.y * 128;
    const int cBase = blockIdx.x * 128;
    const int tid = threadIdx.x;
    const int warp = tid >> 5, lane = tid & 31;
    const int wr = warp >> 2, wc = warp & 3;

    FragC16 acc[4][2];
#pragma unroll
    for (int i = 0; i < 4; i++)
#pragma unroll
        for (int j = 0; j < 2; j++) wmma::fill_fragment(acc[i][j], 0.f);

    issue_Ah(As[0], A, mBase, 0, DD, tid);
    issue_Bh(Bs[0], g_wout, 0, cBase, DD, tid);
    CP_COMMIT();
    int buf = 0;
    for (int kt = 0; kt < 256; kt += 32) {
        CP_WAIT0();
        __syncthreads();
        if (kt + 32 < 256) {
            issue_Ah(As[buf ^ 1], A, mBase, kt + 32, DD, tid);
            issue_Bh(Bs[buf ^ 1], g_wout, kt + 32, cBase, DD, tid);
            CP_COMMIT();
        }
        gemm_core_h(As[buf], Bs[buf], acc, wr, wc);
        buf ^= 1;
    }
    __syncthreads();

    float* stg = (float*)As + warp * (16 * ST_LD);
    const int r = lane >> 1, c0 = (lane & 1) * 8;
#pragma unroll
    for (int i = 0; i < 4; i++)
#pragma unroll
        for (int j = 0; j < 2; j++) {
            wmma::store_matrix_sync(stg, acc[i][j], ST_LD, wmma::mem_row_major);
            __syncwarp();
            int gm = mBase + wr * 64 + i * 16 + r;
            int gc = cBase + wc * 32 + j * 16 + c0;
            const float* sp = stg + r * ST_LD + c0;
            __half* dst = g_m[s] + (size_t)gm * DD + gc;
#pragma unroll
            for (int u = 0; u < 8; u += 2)
                *(__half2*)(dst + u) =
                    __floats2half2_rn(sp[u] + bias[gc + u], sp[u + 1] + bias[gc + u + 1]);
            __syncwarp();
        }
}

// ==========================================================================
// Kernel 4: FFN1.  h = [x | m] @ w_f1 + b_f1  (K=512) -> f32 g_h. grid (4,64,2)
// ==========================================================================
__global__ __launch_bounds__(256) void ffn1_kernel(const float* __restrict__ bias)
{
    __shared__ __align__(16) __half As[2][128 * ASH_LD];
    __shared__ __align__(16) __half Bs[2][32 * BSH_LD];

    const int s = blockIdx.z;
    const __half* X  = g_xh[s];
    const __half* Mm = g_m[s];
    const int mBase = blockIdx.y * 128;
    const int cBase = blockIdx.x * 128;
    const int tid = threadIdx.x;
    const int warp = tid >> 5, lane = tid & 31;
    const int wr = warp >> 2, wc = warp & 3;

    FragC16 acc[4][2];
#pragma unroll
    for (int i = 0; i < 4; i++)
#pragma unroll
        for (int j = 0; j < 2; j++) wmma::fill_fragment(acc[i][j], 0.f);

    issue_Ah(As[0], X, mBase, 0, DD, tid);
    issue_Bh(Bs[0], g_wf1, 0, cBase, 2 * DD, tid);
    CP_COMMIT();
    int buf = 0;
    for (int kt = 0; kt < 512; kt += 32) {
        CP_WAIT0();
        __syncthreads();
        if (kt + 32 < 512) {
            int kn = kt + 32;
            const __half* Asrc = (kn < 256) ? X : Mm;
            int kOff = (kn < 256) ? kn : kn - 256;
            issue_Ah(As[buf ^ 1], Asrc, mBase, kOff, DD, tid);
            issue_Bh(Bs[buf ^ 1], g_wf1, kn, cBase, 2 * DD, tid);
            CP_COMMIT();
        }
        gemm_core_h(As[buf], Bs[buf], acc, wr, wc);
        buf ^= 1;
    }
    __syncthreads();

    float* stg = (float*)As + warp * (16 * ST_LD);
    const int r = lane >> 1, c0 = (lane & 1) * 8;
#pragma unroll
    for (int i = 0; i < 4; i++)
#pragma unroll
        for (int j = 0; j < 2; j++) {
            wmma::store_matrix_sync(stg, acc[i][j], ST_LD, wmma::mem_row_major);
            __syncwarp();
            int gm = mBase + wr * 64 + i * 16 + r;
            int gc = cBase + wc * 32 + j * 16 + c0;
            float4 b0 = *(const float4*)(bias + gc);
            float4 b1 = *(const float4*)(bias + gc + 4);
            const float* sp = stg + r * ST_LD + c0;
            float4 v0 = make_float4(sp[0] + b0.x, sp[1] + b0.y, sp[2] + b0.z, sp[3] + b0.w);
            float4 v1 = make_float4(sp[4] + b1.x, sp[5] + b1.y, sp[6] + b1.z, sp[7] + b1.w);
            *(float4*)(&g_h[s][(size_t)gm * (2 * DD) + gc])     = v0;
            *(float4*)(&g_h[s][(size_t)gm * (2 * DD) + gc + 4]) = v1;
            __syncwarp();
        }
}

// ==========================================================================
// Kernel 5: LayerNorm(512) + exact GELU; f32 in g_h -> half g_hh.
// grid 16384 block 128
// ==========================================================================
__global__ __launch_bounds__(128) void ln_gelu_kernel(
    const float* __restrict__ g, const float* __restrict__ bta)
{
    const int row = blockIdx.x;
    const int s = row >> 13;
    const int rr = row & 8191;
    const float* h = g_h[s] + (size_t)rr * 512;
    const int tid = threadIdx.x;

    float4 t = reinterpret_cast<const float4*>(h)[tid];
    float sum = t.x + t.y + t.z + t.w;
    float sq  = t.x * t.x + t.y * t.y + t.z * t.z + t.w * t.w;
#pragma unroll
    for (int off = 16; off > 0; off >>= 1) {
        sum += __shfl_xor_sync(0xffffffffu, sum, off);
        sq  += __shfl_xor_sync(0xffffffffu, sq,  off);
    }
    __shared__ float ssum[4], ssq[4];
    const int w = tid >> 5;
    if ((tid & 31) == 0) { ssum[w] = sum; ssq[w] = sq; }
    __syncthreads();
    sum = ssum[0] + ssum[1] + ssum[2] + ssum[3];
    sq  = ssq[0]  + ssq[1]  + ssq[2]  + ssq[3];

    const float mu   = sum * (1.f / 512.f);
    const float var  = sq * (1.f / 512.f) - mu * mu;
    const float rstd = rsqrtf(var + 1e-5f);

    float4 gg = reinterpret_cast<const float4*>(g)[tid];
    float4 bb = reinterpret_cast<const float4*>(bta)[tid];
    auto act = [&](float v, float gv, float bv) {
        float y = (v - mu) * rstd * gv + bv;
        return 0.5f * y * (1.f + erff(y * 0.70710678118654752f));
    };
    float r0 = act(t.x, gg.x, bb.x);
    float r1 = act(t.y, gg.y, bb.y);
    float r2 = act(t.z, gg.z, bb.z);
    float r3 = act(t.w, gg.w, bb.w);

    __half2* dst = (__half2*)(g_hh[s] + (size_t)rr * 512 + tid * 4);
    dst[0] = __floats2half2_rn(r0, r1);
    dst[1] = __floats2half2_rn(r2, r3);
}

// ==========================================================================
// Kernel 6: FFN2 + residual.  out = x + hh @ w_f2 + b_f2 (K=512). grid (2,64,2)
// ==========================================================================
__global__ __launch_bounds__(256) void ffn2_kernel(
    const float* __restrict__ x0, const float* __restrict__ x1,
    const float* __restrict__ bias, float* __restrict__ out)
{
    __shared__ __align__(16) __half As[2][128 * ASH_LD];
    __shared__ __align__(16) __half Bs[2][32 * BSH_LD];

    const int s = blockIdx.z;
    const float* X = s ? x1 : x0;
    const __half* A = g_hh[s];
    const int mBase = blockIdx.y * 128;
    const int cBase = blockIdx.x * 128;
    const int tid = threadIdx.x;
    const int warp = tid >> 5, lane = tid & 31;
    const int wr = warp >> 2, wc = warp & 3;

    FragC16 acc[4][2];
#pragma unroll
    for (int i = 0; i < 4; i++)
#pragma unroll
        for (int j = 0; j < 2; j++) wmma::fill_fragment(acc[i][j], 0.f);

    issue_Ah(As[0], A, mBase, 0, 2 * DD, tid);
    issue_Bh(Bs[0], g_wf2, 0, cBase, DD, tid);
    CP_COMMIT();
    int buf = 0;
    for (int kt = 0; kt < 512; kt += 32) {
        CP_WAIT0();
        __syncthreads();
        if (kt + 32 < 512) {
            issue_Ah(As[buf ^ 1], A, mBase, kt + 32, 2 * DD, tid);
            issue_Bh(Bs[buf ^ 1], g_wf2, kt + 32, cBase, DD, tid);
            CP_COMMIT();
        }
        gemm_core_h(As[buf], Bs[buf], acc, wr, wc);
        buf ^= 1;
    }
    __syncthreads();

    float* stg = (float*)As + warp * (16 * ST_LD);
    const int r = lane >> 1, c0 = (lane & 1) * 8;
#pragma unroll
    for (int i = 0; i < 4; i++)
#pragma unroll
        for (int j = 0; j < 2; j++) {
            wmma::store_matrix_sync(stg, acc[i][j], ST_LD, wmma::mem_row_major);
            __syncwarp();
            int gm = mBase + wr * 64 + i * 16 + r;
            int gc = cBase + wc * 32 + j * 16 + c0;
            float4 b0 = *(const float4*)(bias + gc);
            float4 b1 = *(const float4*)(bias + gc + 4);
            float4 x0v = *(const float4*)(X + (size_t)gm * DD + gc);
            float4 x1v = *(const float4*)(X + (size_t)gm * DD + gc + 4);
            const float* sp = stg + r * ST_LD + c0;
            float4 v0 = make_float4(sp[0] + b0.x + x0v.x, sp[1] + b0.y + x0v.y,
                                    sp[2] + b0.z + x0v.z, sp[3] + b0.w + x0v.w);
            float4 v1 = make_float4(sp[4] + b1.x + x1v.x, sp[5] + b1.y + x1v.y,
                                    sp[6] + b1.z + x1v.z, sp[7] + b1.w + x1v.w);
            *(float4*)(out + (size_t)s * MTOT * DD + (size_t)gm * DD + gc)     = v0;
            *(float4*)(out + (size_t)s * MTOT * DD + (size_t)gm * DD + gc + 4) = v1;
            __syncwarp();
        }
}

// ==========================================================================
extern "C" void kernel_launch(void* const* d_in, const int* in_sizes, int n_in,
                              void* d_out, int out_size)
{
    const float* x0    = (const float*)d_in[0];
    const float* x1    = (const float*)d_in[1];
    const float* w_qk  = (const float*)d_in[2];
    const float* b_qk  = (const float*)d_in[3];
    const float* w_v   = (const float*)d_in[4];
    const float* b_v   = (const float*)d_in[5];
    const float* w_out = (const float*)d_in[6];
    const float* b_out = (const float*)d_in[7];
    const float* w_f1  = (const float*)d_in[8];
    const float* b_f1  = (const float*)d_in[9];
    const float* ln_g  = (const float*)d_in[10];
    const float* ln_b  = (const float*)d_in[11];
    const float* w_f2  = (const float*)d_in[12];
    const float* b_f2  = (const float*)d_in[13];
    float* out = (float*)d_out;

    cudaFuncSetAttribute(attn_kernel,
                         cudaFuncAttributeMaxDynamicSharedMemorySize, ATTN_SMEM);

    cvt_kernel    <<<dim3(2048, 7), 256>>>(x0, x1, w_qk, w_v, w_out, w_f1, w_f2);
    qkv_kernel    <<<dim3(4, 64, 2), 256>>>(b_qk, b_v);
    attn_kernel   <<<dim3(16, 16, 2), 256, ATTN_SMEM>>>();
    outproj_kernel<<<dim3(2, 64, 2), 256>>>(b_out);
    ffn1_kernel   <<<dim3(4, 64, 2), 256>>>(b_f1);
    ln_gelu_kernel<<<16384, 128>>>(ln_g, ln_b);
    ffn2_kernel   <<<dim3(2, 64, 2), 256>>>(x0, x1, b_f2, out);
}